// round 1
// baseline (speedup 1.0000x reference)
#include <cuda_runtime.h>
#include <math.h>

#define NB 8
#define NV 8192
#define NK 128
#define NC 256
#define NN 65536          // NB*NV
#define NNZ 1048576       // 16*NN
#define BNEPS 1e-5f

// ------------------------- scratch (device globals) -------------------------
static __device__ float d_xspec[NB*NK*NC];   // 1 MB  (atomic accumulated)
static __device__ float d_y   [NB*NK*NC];    // coefs * xspec
static __device__ float d_xd  [NN*NC];       // x_diffuse
static __device__ float d_gX  [NN*NC];
static __device__ float d_gY  [NN*NC];
static __device__ float d_gf  [NN*NC];       // grad_feat
static __device__ float d_h0  [NN*NC];       // also temp bre
static __device__ float d_h1  [NN*NC];       // also temp bim
static __device__ float d_h2  [NN*NC];
static __device__ float d_stats[1536];       // [sum0,sq0,sum1,sq1,sum2,sq2] x256

// ------------------------------- zero init ----------------------------------
__global__ void k_zero() {
    int i = (blockIdx.x * 256 + threadIdx.x) * 4;
    float4 z = make_float4(0.f, 0.f, 0.f, 0.f);
    *(float4*)&d_gX[i] = z;
    *(float4*)&d_gY[i] = z;
    if (i < NB*NK*NC) *(float4*)&d_xspec[i] = z;
    if (i < 1536)     *(float4*)&d_stats[i] = z;
}

// ---------------------------------------------------------------------------
// x_spec[b,k,c] = sum_v mass[b,v]*evecs[b,v,k]*x[b,v,c]
// split-V partial GEMM with atomic accumulation. grid (16, 2, 8)
// ---------------------------------------------------------------------------
__global__ __launch_bounds__(256) void k_xspec(
    const float* __restrict__ x, const float* __restrict__ mass,
    const float* __restrict__ evecs)
{
    int vc = blockIdx.x, ch = blockIdx.y, b = blockIdx.z;
    int v0 = vc * 512;
    int tid = threadIdx.x;
    int tx = tid & 15, ty = tid >> 4;

    __shared__ __align__(16) float As[8][136];  // [v][k]
    __shared__ __align__(16) float Bs[8][136];  // [v][c]

    float acc[8][8];
#pragma unroll
    for (int i = 0; i < 8; i++)
#pragma unroll
        for (int j = 0; j < 8; j++) acc[i][j] = 0.f;

    const float* evb = evecs + (size_t)(b*NV + v0) * NK;
    const float* xb  = x     + (size_t)(b*NV + v0) * NC + ch*128;
    const float* mb  = mass + b*NV + v0;

    for (int vs = 0; vs < 512; vs += 8) {
#pragma unroll
        for (int i = 0; i < 4; i++) {
            int e = tid + i*256;
            int vv = e >> 7, kx = e & 127;
            As[vv][kx] = evb[(size_t)(vs+vv)*NK + kx] * mb[vs+vv];
        }
#pragma unroll
        for (int i = 0; i < 4; i++) {
            int e = tid + i*256;
            int vv = e >> 7, c = e & 127;
            Bs[vv][c] = xb[(size_t)(vs+vv)*NC + c];
        }
        __syncthreads();
#pragma unroll
        for (int kk = 0; kk < 8; kk++) {
            float a[8], bb[8];
            *(float4*)(a)    = *(const float4*)&As[kk][ty*4];
            *(float4*)(a+4)  = *(const float4*)&As[kk][64 + ty*4];
            *(float4*)(bb)   = *(const float4*)&Bs[kk][tx*4];
            *(float4*)(bb+4) = *(const float4*)&Bs[kk][64 + tx*4];
#pragma unroll
            for (int i = 0; i < 8; i++)
#pragma unroll
                for (int j = 0; j < 8; j++) acc[i][j] += a[i] * bb[j];
        }
        __syncthreads();
    }
#pragma unroll
    for (int i = 0; i < 8; i++) {
        int kr = (i < 4) ? ty*4 + i : 64 + ty*4 + (i-4);
#pragma unroll
        for (int j = 0; j < 8; j++) {
            int c = (j < 4) ? tx*4 + j : 64 + tx*4 + (j-4);
            atomicAdd(&d_xspec[(b*NK + kr)*NC + ch*128 + c], acc[i][j]);
        }
    }
}

// y[b,k,c] = exp(-evals[b,k]*max(t[c],1e-8)) * xspec
__global__ void k_coef(const float* __restrict__ evals, const float* __restrict__ dt) {
    int i = blockIdx.x * 256 + threadIdx.x;  // < 262144
    int c = i & 255;
    int bk = i >> 8;
    float t = fmaxf(dt[c], 1e-8f);
    d_y[i] = expf(-evals[bk] * t) * d_xspec[i];
}

// ---------------------------------------------------------------------------
// x_diffuse[b,v,c] = sum_k evecs[b,v,k] * y[b,k,c].  grid (64, 2, 8)
// ---------------------------------------------------------------------------
__global__ __launch_bounds__(256) void k_xdiff(const float* __restrict__ evecs) {
    int rb = blockIdx.x, ch = blockIdx.y, b = blockIdx.z;
    int tid = threadIdx.x;
    int tx = tid & 15, ty = tid >> 4;

    __shared__ __align__(16) float As[8][136];  // [k][row]
    __shared__ __align__(16) float Bs[8][136];  // [k][c]

    float acc[8][8];
#pragma unroll
    for (int i = 0; i < 8; i++)
#pragma unroll
        for (int j = 0; j < 8; j++) acc[i][j] = 0.f;

    int row0 = b*NV + rb*128;
    int r = tid >> 1, kq = (tid & 1) * 4;
    const float* yB = d_y + b*NK*NC + ch*128;

    for (int k0 = 0; k0 < NK; k0 += 8) {
        float4 av = *(const float4*)&evecs[(size_t)(row0 + r)*NK + k0 + kq];
        As[kq+0][r] = av.x; As[kq+1][r] = av.y; As[kq+2][r] = av.z; As[kq+3][r] = av.w;
#pragma unroll
        for (int i = 0; i < 4; i++) {
            int e = tid + i*256;
            int kk = e >> 7, c = e & 127;
            Bs[kk][c] = yB[(k0+kk)*NC + c];
        }
        __syncthreads();
#pragma unroll
        for (int kk = 0; kk < 8; kk++) {
            float a[8], bb[8];
            *(float4*)(a)    = *(const float4*)&As[kk][ty*4];
            *(float4*)(a+4)  = *(const float4*)&As[kk][64 + ty*4];
            *(float4*)(bb)   = *(const float4*)&Bs[kk][tx*4];
            *(float4*)(bb+4) = *(const float4*)&Bs[kk][64 + tx*4];
#pragma unroll
            for (int i = 0; i < 8; i++)
#pragma unroll
                for (int j = 0; j < 8; j++) acc[i][j] += a[i] * bb[j];
        }
        __syncthreads();
    }
#pragma unroll
    for (int i = 0; i < 8; i++) {
        int row = (i < 4) ? ty*4 + i : 64 + ty*4 + (i-4);
        float4 v0 = make_float4(acc[i][0], acc[i][1], acc[i][2], acc[i][3]);
        float4 v1 = make_float4(acc[i][4], acc[i][5], acc[i][6], acc[i][7]);
        *(float4*)&d_xd[(size_t)(row0+row)*NC + ch*128 + tx*4]      = v0;
        *(float4*)&d_xd[(size_t)(row0+row)*NC + ch*128 + 64 + tx*4] = v1;
    }
}

// ---------------------------------------------------------------------------
// SpMM scatter: out[rows[e], :] += vals[e] * xd[cols[e], :]
// 64 threads per nnz, 4 channels each. grid 262144, block 256
// ---------------------------------------------------------------------------
__global__ void k_spmm(const int* __restrict__ rows, const int* __restrict__ cols,
                       const float* __restrict__ vals, int which) {
    int tid = threadIdx.x;
    int e = blockIdx.x * 4 + (tid >> 6);
    int c = (tid & 63) * 4;
    int r  = rows[e];
    int cl = cols[e];
    float v = vals[e];
    float* out = which ? d_gY : d_gX;
    float4 s = *(const float4*)&d_xd[(size_t)cl * NC + c];
    float* o = out + (size_t)r * NC + c;
    atomicAdd(o + 0, v * s.x);
    atomicAdd(o + 1, v * s.y);
    atomicAdd(o + 2, v * s.z);
    atomicAdd(o + 3, v * s.w);
}

// ---------------------------------------------------------------------------
// MODE 0: d_h0 = gX@Are^T - gY@Aim^T   (bre)
// MODE 1: d_h1 = gY@Are^T + gX@Aim^T   (bim)
// grid (512, 2)
// ---------------------------------------------------------------------------
template<int MODE>
__global__ __launch_bounds__(256) void k_cplx(const float* __restrict__ Are,
                                              const float* __restrict__ Aim) {
    const float* A1 = MODE ? d_gY : d_gX;
    const float* A2 = MODE ? d_gX : d_gY;
    float* out = MODE ? d_h1 : d_h0;

    int rb = blockIdx.x, ch = blockIdx.y;
    int tid = threadIdx.x;
    int tx = tid & 15, ty = tid >> 4;

    __shared__ __align__(16) float A1s[8][136];
    __shared__ __align__(16) float A2s[8][136];
    __shared__ __align__(16) float B1s[8][136];
    __shared__ __align__(16) float B2s[8][136];

    float acc[8][8];
#pragma unroll
    for (int i = 0; i < 8; i++)
#pragma unroll
        for (int j = 0; j < 8; j++) acc[i][j] = 0.f;

    int row0 = rb * 128;
    int m0 = ch * 128;
    int r = tid >> 1, kq = (tid & 1) * 4;

    for (int k0 = 0; k0 < NC; k0 += 8) {
        float4 a1 = *(const float4*)&A1[(size_t)(row0 + r)*NC + k0 + kq];
        float4 a2 = *(const float4*)&A2[(size_t)(row0 + r)*NC + k0 + kq];
        float4 b1 = *(const float4*)&Are[(size_t)(m0 + r)*NC + k0 + kq];
        float4 b2 = *(const float4*)&Aim[(size_t)(m0 + r)*NC + k0 + kq];
        A1s[kq+0][r] = a1.x; A1s[kq+1][r] = a1.y; A1s[kq+2][r] = a1.z; A1s[kq+3][r] = a1.w;
        A2s[kq+0][r] = a2.x; A2s[kq+1][r] = a2.y; A2s[kq+2][r] = a2.z; A2s[kq+3][r] = a2.w;
        B1s[kq+0][r] = b1.x; B1s[kq+1][r] = b1.y; B1s[kq+2][r] = b1.z; B1s[kq+3][r] = b1.w;
        B2s[kq+0][r] = b2.x; B2s[kq+1][r] = b2.y; B2s[kq+2][r] = b2.z; B2s[kq+3][r] = b2.w;
        __syncthreads();
#pragma unroll
        for (int kk = 0; kk < 8; kk++) {
            float a1v[8], a2v[8], b1v[8], b2v[8];
            *(float4*)(a1v)   = *(const float4*)&A1s[kk][ty*4];
            *(float4*)(a1v+4) = *(const float4*)&A1s[kk][64 + ty*4];
            *(float4*)(a2v)   = *(const float4*)&A2s[kk][ty*4];
            *(float4*)(a2v+4) = *(const float4*)&A2s[kk][64 + ty*4];
            *(float4*)(b1v)   = *(const float4*)&B1s[kk][tx*4];
            *(float4*)(b1v+4) = *(const float4*)&B1s[kk][64 + tx*4];
            *(float4*)(b2v)   = *(const float4*)&B2s[kk][tx*4];
            *(float4*)(b2v+4) = *(const float4*)&B2s[kk][64 + tx*4];
#pragma unroll
            for (int i = 0; i < 8; i++)
#pragma unroll
                for (int j = 0; j < 8; j++) {
                    acc[i][j] += a1v[i] * b1v[j];
                    if (MODE) acc[i][j] += a2v[i] * b2v[j];
                    else      acc[i][j] -= a2v[i] * b2v[j];
                }
        }
        __syncthreads();
    }
#pragma unroll
    for (int i = 0; i < 8; i++) {
        int row = (i < 4) ? ty*4 + i : 64 + ty*4 + (i-4);
        float4 v0 = make_float4(acc[i][0], acc[i][1], acc[i][2], acc[i][3]);
        float4 v1 = make_float4(acc[i][4], acc[i][5], acc[i][6], acc[i][7]);
        *(float4*)&out[(size_t)(row0+row)*NC + m0 + tx*4]      = v0;
        *(float4*)&out[(size_t)(row0+row)*NC + m0 + 64 + tx*4] = v1;
    }
}

// grad_feat = tanh(gX*bre + gY*bim)
__global__ void k_tanh() {
    size_t i = (size_t)(blockIdx.x * 256 + threadIdx.x) * 4;
    float4 gx = *(float4*)&d_gX[i];
    float4 gy = *(float4*)&d_gY[i];
    float4 br = *(float4*)&d_h0[i];
    float4 bi = *(float4*)&d_h1[i];
    float4 o;
    o.x = tanhf(gx.x * br.x + gy.x * bi.x);
    o.y = tanhf(gx.y * br.y + gy.y * bi.y);
    o.z = tanhf(gx.z * br.z + gy.z * bi.z);
    o.w = tanhf(gx.w * br.w + gy.w * bi.w);
    *(float4*)&d_gf[i] = o;
}

// ---------------------------------------------------------------------------
// h0 = [x | xd | gf] @ W0 + b0    (virtual concat, KD = 768). grid (512, 2)
// ---------------------------------------------------------------------------
__global__ __launch_bounds__(256) void k_gemm0(const float* __restrict__ x,
                                               const float* __restrict__ W0,
                                               const float* __restrict__ b0) {
    int rb = blockIdx.x, ch = blockIdx.y;
    int tid = threadIdx.x;
    int tx = tid & 15, ty = tid >> 4;

    __shared__ __align__(16) float As[8][136];
    __shared__ __align__(16) float Bs[8][136];

    float acc[8][8];
#pragma unroll
    for (int i = 0; i < 8; i++)
#pragma unroll
        for (int j = 0; j < 8; j++) acc[i][j] = 0.f;

    int row0 = rb * 128;
    int m0 = ch * 128;
    int r = tid >> 1, kq = (tid & 1) * 4;

    for (int k0 = 0; k0 < 768; k0 += 8) {
        int piece = k0 >> 8;
        const float* Abase = (piece == 0) ? x : ((piece == 1) ? (const float*)d_xd : (const float*)d_gf);
        int kloc = (k0 & 255) + kq;
        float4 av = *(const float4*)&Abase[(size_t)(row0 + r)*NC + kloc];
        As[kq+0][r] = av.x; As[kq+1][r] = av.y; As[kq+2][r] = av.z; As[kq+3][r] = av.w;
#pragma unroll
        for (int i = 0; i < 4; i++) {
            int e = tid + i*256;
            int kk = e >> 7, c = e & 127;
            Bs[kk][c] = W0[(size_t)(k0+kk)*NC + m0 + c];
        }
        __syncthreads();
#pragma unroll
        for (int kk = 0; kk < 8; kk++) {
            float a[8], bb[8];
            *(float4*)(a)    = *(const float4*)&As[kk][ty*4];
            *(float4*)(a+4)  = *(const float4*)&As[kk][64 + ty*4];
            *(float4*)(bb)   = *(const float4*)&Bs[kk][tx*4];
            *(float4*)(bb+4) = *(const float4*)&Bs[kk][64 + tx*4];
#pragma unroll
            for (int i = 0; i < 8; i++)
#pragma unroll
                for (int j = 0; j < 8; j++) acc[i][j] += a[i] * bb[j];
        }
        __syncthreads();
    }
#pragma unroll
    for (int i = 0; i < 8; i++) {
        int row = (i < 4) ? ty*4 + i : 64 + ty*4 + (i-4);
        float4 v0 = make_float4(acc[i][0] + b0[m0+tx*4+0], acc[i][1] + b0[m0+tx*4+1],
                                acc[i][2] + b0[m0+tx*4+2], acc[i][3] + b0[m0+tx*4+3]);
        float4 v1 = make_float4(acc[i][4] + b0[m0+64+tx*4+0], acc[i][5] + b0[m0+64+tx*4+1],
                                acc[i][6] + b0[m0+64+tx*4+2], acc[i][7] + b0[m0+64+tx*4+3]);
        *(float4*)&d_h0[(size_t)(row0+row)*NC + m0 + tx*4]      = v0;
        *(float4*)&d_h0[(size_t)(row0+row)*NC + m0 + 64 + tx*4] = v1;
    }
}

// column sum & sumsq. grid 256, block 256
__global__ void k_stats(int stage) {
    const float* M = (stage == 0) ? d_h0 : (stage == 1) ? d_h1 : d_h2;
    float* sums = d_stats + stage * 512;
    float* sqs  = sums + 256;
    int c = threadIdx.x;
    int r0 = blockIdx.x * 256;
    float s = 0.f, q = 0.f;
    for (int r = 0; r < 256; r++) {
        float v = M[(size_t)(r0 + r) * NC + c];
        s += v;
        q += v * v;
    }
    atomicAdd(&sums[c], s);
    atomicAdd(&sqs[c],  q);
}

// ---------------------------------------------------------------------------
// out = relu(bn(A)) @ W + bias, with bn folded into the A-load.
// stage 1: A=d_h0 (stats0) -> d_h1;  stage 2: A=d_h1 (stats1) -> d_h2
// ---------------------------------------------------------------------------
__global__ __launch_bounds__(256) void k_gemm_bn(const float* __restrict__ W,
                                                 const float* __restrict__ bias,
                                                 const float* __restrict__ g,
                                                 const float* __restrict__ be,
                                                 int stage) {
    const float* A = (stage == 1) ? d_h0 : d_h1;
    float* out     = (stage == 1) ? d_h1 : d_h2;
    const float* st = d_stats + (stage - 1) * 512;

    int tid = threadIdx.x;
    __shared__ float sscale[256], sshift[256];
    {
        float mean = st[tid] * (1.0f / NN);
        float var  = st[256 + tid] * (1.0f / NN) - mean * mean;
        float sc = rsqrtf(var + BNEPS) * g[tid];
        sscale[tid] = sc;
        sshift[tid] = be[tid] - mean * sc;
    }
    __syncthreads();

    int rb = blockIdx.x, ch = blockIdx.y;
    int tx = tid & 15, ty = tid >> 4;

    __shared__ __align__(16) float As[8][136];
    __shared__ __align__(16) float Bs[8][136];

    float acc[8][8];
#pragma unroll
    for (int i = 0; i < 8; i++)
#pragma unroll
        for (int j = 0; j < 8; j++) acc[i][j] = 0.f;

    int row0 = rb * 128;
    int m0 = ch * 128;
    int r = tid >> 1, kq = (tid & 1) * 4;

    for (int k0 = 0; k0 < NC; k0 += 8) {
        int kg = k0 + kq;
        float4 av = *(const float4*)&A[(size_t)(row0 + r)*NC + kg];
        av.x = fmaxf(av.x * sscale[kg+0] + sshift[kg+0], 0.f);
        av.y = fmaxf(av.y * sscale[kg+1] + sshift[kg+1], 0.f);
        av.z = fmaxf(av.z * sscale[kg+2] + sshift[kg+2], 0.f);
        av.w = fmaxf(av.w * sscale[kg+3] + sshift[kg+3], 0.f);
        As[kq+0][r] = av.x; As[kq+1][r] = av.y; As[kq+2][r] = av.z; As[kq+3][r] = av.w;
#pragma unroll
        for (int i = 0; i < 4; i++) {
            int e = tid + i*256;
            int kk = e >> 7, c = e & 127;
            Bs[kk][c] = W[(size_t)(k0+kk)*NC + m0 + c];
        }
        __syncthreads();
#pragma unroll
        for (int kk = 0; kk < 8; kk++) {
            float a[8], bb[8];
            *(float4*)(a)    = *(const float4*)&As[kk][ty*4];
            *(float4*)(a+4)  = *(const float4*)&As[kk][64 + ty*4];
            *(float4*)(bb)   = *(const float4*)&Bs[kk][tx*4];
            *(float4*)(bb+4) = *(const float4*)&Bs[kk][64 + tx*4];
#pragma unroll
            for (int i = 0; i < 8; i++)
#pragma unroll
                for (int j = 0; j < 8; j++) acc[i][j] += a[i] * bb[j];
        }
        __syncthreads();
    }
#pragma unroll
    for (int i = 0; i < 8; i++) {
        int row = (i < 4) ? ty*4 + i : 64 + ty*4 + (i-4);
        float4 v0 = make_float4(acc[i][0] + bias[m0+tx*4+0], acc[i][1] + bias[m0+tx*4+1],
                                acc[i][2] + bias[m0+tx*4+2], acc[i][3] + bias[m0+tx*4+3]);
        float4 v1 = make_float4(acc[i][4] + bias[m0+64+tx*4+0], acc[i][5] + bias[m0+64+tx*4+1],
                                acc[i][6] + bias[m0+64+tx*4+2], acc[i][7] + bias[m0+64+tx*4+3]);
        *(float4*)&out[(size_t)(row0+row)*NC + m0 + tx*4]      = v0;
        *(float4*)&out[(size_t)(row0+row)*NC + m0 + 64 + tx*4] = v1;
    }
}

// out = bn(h2) + x  (stats stage 2, gamma/beta 2)
__global__ void k_final(const float* __restrict__ x, const float* __restrict__ g,
                        const float* __restrict__ be, float* __restrict__ out) {
    int tid = threadIdx.x;
    __shared__ float sc[256], sh[256];
    {
        float mean = d_stats[1024 + tid] * (1.0f / NN);
        float var  = d_stats[1280 + tid] * (1.0f / NN) - mean * mean;
        float s = rsqrtf(var + BNEPS) * g[tid];
        sc[tid] = s;
        sh[tid] = be[tid] - mean * s;
    }
    __syncthreads();
    size_t i = (size_t)(blockIdx.x * 256 + tid) * 4;
    int c = (int)(i & 255);
    float4 h  = *(float4*)&d_h2[i];
    float4 xv = *(const float4*)&x[i];
    float4 o;
    o.x = h.x * sc[c+0] + sh[c+0] + xv.x;
    o.y = h.y * sc[c+1] + sh[c+1] + xv.y;
    o.z = h.z * sc[c+2] + sh[c+2] + xv.z;
    o.w = h.w * sc[c+3] + sh[c+3] + xv.w;
    *(float4*)&out[i] = o;
}

// ------------------------------- launch --------------------------------------
extern "C" void kernel_launch(void* const* d_in, const int* in_sizes, int n_in,
                              void* d_out, int out_size) {
    const float* x       = (const float*)d_in[0];
    const float* mass    = (const float*)d_in[1];
    const float* evals   = (const float*)d_in[2];
    const float* evecs   = (const float*)d_in[3];
    const int*   gx_rows = (const int*)  d_in[4];
    const int*   gx_cols = (const int*)  d_in[5];
    const float* gx_vals = (const float*)d_in[6];
    const int*   gy_rows = (const int*)  d_in[7];
    const int*   gy_cols = (const int*)  d_in[8];
    const float* gy_vals = (const float*)d_in[9];
    const float* dt      = (const float*)d_in[10];
    const float* A_re    = (const float*)d_in[11];
    const float* A_im    = (const float*)d_in[12];
    const float* W0      = (const float*)d_in[13];
    const float* b0      = (const float*)d_in[14];
    const float* g0      = (const float*)d_in[15];
    const float* be0     = (const float*)d_in[16];
    const float* W1      = (const float*)d_in[17];
    const float* b1      = (const float*)d_in[18];
    const float* g1      = (const float*)d_in[19];
    const float* be1     = (const float*)d_in[20];
    const float* W2      = (const float*)d_in[21];
    const float* b2      = (const float*)d_in[22];
    const float* g2      = (const float*)d_in[23];
    const float* be2     = (const float*)d_in[24];
    float* out = (float*)d_out;

    k_zero<<<16384, 256>>>();
    k_xspec<<<dim3(16, 2, 8), 256>>>(x, mass, evecs);
    k_coef<<<1024, 256>>>(evals, dt);
    k_xdiff<<<dim3(64, 2, 8), 256>>>(evecs);
    k_spmm<<<NNZ/4, 256>>>(gx_rows, gx_cols, gx_vals, 0);
    k_spmm<<<NNZ/4, 256>>>(gy_rows, gy_cols, gy_vals, 1);
    k_cplx<0><<<dim3(512, 2), 256>>>(A_re, A_im);
    k_cplx<1><<<dim3(512, 2), 256>>>(A_re, A_im);
    k_tanh<<<16384, 256>>>();
    k_gemm0<<<dim3(512, 2), 256>>>(x, W0, b0);
    k_stats<<<256, 256>>>(0);
    k_gemm_bn<<<dim3(512, 2), 256>>>(W1, b1, g0, be0, 1);
    k_stats<<<256, 256>>>(1);
    k_gemm_bn<<<dim3(512, 2), 256>>>(W2, b2, g1, be1, 2);
    k_stats<<<256, 256>>>(2);
    k_final<<<16384, 256>>>(x, g2, be2, out);
}

// round 3
// speedup vs baseline: 1.3258x; 1.3258x over previous
#include <cuda_runtime.h>
#include <cuda_bf16.h>
#include <math.h>
#include <cstdint>

#define NB 8
#define NV 8192
#define NK 128
#define NC 256
#define NN 65536          // NB*NV
#define NNZ 1048576       // 16*NN
#define BNEPS 1e-5f

// ------------------------- scratch (device globals) -------------------------
static __device__ float d_xspec[NB*NK*NC];
static __device__ float d_y   [NB*NK*NC];
static __device__ float d_xd  [NN*NC];
static __device__ float d_gX  [NN*NC];
static __device__ float d_gY  [NN*NC];
static __device__ float d_bb  [(size_t)NN*512];  // [bre | bim]
static __device__ float d_h0  [NN*NC];
static __device__ float d_h1  [NN*NC];
static __device__ float d_h2  [NN*NC];
static __device__ float d_stats[1536];
// bf16 split A: [NN, 768] hi/lo
static __device__ __nv_bfloat16 d_Ah[(size_t)NN*768];
static __device__ __nv_bfloat16 d_Al[(size_t)NN*768];
// bf16 split B pool: cplx(512x512) | W0T(256x768) | W1T(256x256) | W2T(256x256)
#define BOFF_CPLX 0
#define BOFF_W0   262144
#define BOFF_W1   458752
#define BOFF_W2   524288
static __device__ __nv_bfloat16 d_Bh[589824];
static __device__ __nv_bfloat16 d_Bl[589824];

__device__ __forceinline__ void split_store(float v, __nv_bfloat16* ph, __nv_bfloat16* pl) {
    __nv_bfloat16 h = __float2bfloat16(v);
    *ph = h;
    *pl = __float2bfloat16(v - __bfloat162float(h));
}

__device__ __forceinline__ uint32_t smem_u32(const void* p) {
    uint32_t a;
    asm("{ .reg .u64 t; cvta.to.shared.u64 t, %1; cvt.u32.u64 %0, t; }" : "=r"(a) : "l"(p));
    return a;
}

// ------------------------------- zero init ----------------------------------
__global__ void k_zero() {
    int i = (blockIdx.x * 256 + threadIdx.x) * 4;
    float4 z = make_float4(0.f, 0.f, 0.f, 0.f);
    *(float4*)&d_gX[i] = z;
    *(float4*)&d_gY[i] = z;
    if (i < NB*NK*NC) *(float4*)&d_xspec[i] = z;
    if (i < 1536)     *(float4*)&d_stats[i] = z;
}

// ---------------------------------------------------------------------------
// x_spec[b,k,c] = sum_v mass[b,v]*evecs[b,v,k]*x[b,v,c]   grid (16,2,8)
// ---------------------------------------------------------------------------
__global__ __launch_bounds__(256) void k_xspec(
    const float* __restrict__ x, const float* __restrict__ mass,
    const float* __restrict__ evecs)
{
    int vc = blockIdx.x, ch = blockIdx.y, b = blockIdx.z;
    int v0 = vc * 512;
    int tid = threadIdx.x;
    int tx = tid & 15, ty = tid >> 4;

    __shared__ __align__(16) float As[8][136];
    __shared__ __align__(16) float Bs[8][136];

    float acc[8][8];
#pragma unroll
    for (int i = 0; i < 8; i++)
#pragma unroll
        for (int j = 0; j < 8; j++) acc[i][j] = 0.f;

    const float* evb = evecs + (size_t)(b*NV + v0) * NK;
    const float* xb  = x     + (size_t)(b*NV + v0) * NC + ch*128;
    const float* mb  = mass + b*NV + v0;

    for (int vs = 0; vs < 512; vs += 8) {
#pragma unroll
        for (int i = 0; i < 4; i++) {
            int e = tid + i*256;
            int vv = e >> 7, kx = e & 127;
            As[vv][kx] = evb[(size_t)(vs+vv)*NK + kx] * mb[vs+vv];
        }
#pragma unroll
        for (int i = 0; i < 4; i++) {
            int e = tid + i*256;
            int vv = e >> 7, c = e & 127;
            Bs[vv][c] = xb[(size_t)(vs+vv)*NC + c];
        }
        __syncthreads();
#pragma unroll
        for (int kk = 0; kk < 8; kk++) {
            float a[8], bb[8];
            *(float4*)(a)    = *(const float4*)&As[kk][ty*4];
            *(float4*)(a+4)  = *(const float4*)&As[kk][64 + ty*4];
            *(float4*)(bb)   = *(const float4*)&Bs[kk][tx*4];
            *(float4*)(bb+4) = *(const float4*)&Bs[kk][64 + tx*4];
#pragma unroll
            for (int i = 0; i < 8; i++)
#pragma unroll
                for (int j = 0; j < 8; j++) acc[i][j] += a[i] * bb[j];
        }
        __syncthreads();
    }
#pragma unroll
    for (int i = 0; i < 8; i++) {
        int kr = (i < 4) ? ty*4 + i : 64 + ty*4 + (i-4);
#pragma unroll
        for (int j = 0; j < 8; j++) {
            int c = (j < 4) ? tx*4 + j : 64 + tx*4 + (j-4);
            atomicAdd(&d_xspec[(b*NK + kr)*NC + ch*128 + c], acc[i][j]);
        }
    }
}

__global__ void k_coef(const float* __restrict__ evals, const float* __restrict__ dt) {
    int i = blockIdx.x * 256 + threadIdx.x;
    int c = i & 255;
    int bk = i >> 8;
    float t = fmaxf(dt[c], 1e-8f);
    d_y[i] = expf(-evals[bk] * t) * d_xspec[i];
}

// x_diffuse = evecs @ y   grid (64, 2, 8)
__global__ __launch_bounds__(256) void k_xdiff(const float* __restrict__ evecs) {
    int rb = blockIdx.x, ch = blockIdx.y, b = blockIdx.z;
    int tid = threadIdx.x;
    int tx = tid & 15, ty = tid >> 4;

    __shared__ __align__(16) float As[8][136];
    __shared__ __align__(16) float Bs[8][136];

    float acc[8][8];
#pragma unroll
    for (int i = 0; i < 8; i++)
#pragma unroll
        for (int j = 0; j < 8; j++) acc[i][j] = 0.f;

    int row0 = b*NV + rb*128;
    int r = tid >> 1, kq = (tid & 1) * 4;
    const float* yB = d_y + b*NK*NC + ch*128;

    for (int k0 = 0; k0 < NK; k0 += 8) {
        float4 av = *(const float4*)&evecs[(size_t)(row0 + r)*NK + k0 + kq];
        As[kq+0][r] = av.x; As[kq+1][r] = av.y; As[kq+2][r] = av.z; As[kq+3][r] = av.w;
#pragma unroll
        for (int i = 0; i < 4; i++) {
            int e = tid + i*256;
            int kk = e >> 7, c = e & 127;
            Bs[kk][c] = yB[(k0+kk)*NC + c];
        }
        __syncthreads();
#pragma unroll
        for (int kk = 0; kk < 8; kk++) {
            float a[8], bb[8];
            *(float4*)(a)    = *(const float4*)&As[kk][ty*4];
            *(float4*)(a+4)  = *(const float4*)&As[kk][64 + ty*4];
            *(float4*)(bb)   = *(const float4*)&Bs[kk][tx*4];
            *(float4*)(bb+4) = *(const float4*)&Bs[kk][64 + tx*4];
#pragma unroll
            for (int i = 0; i < 8; i++)
#pragma unroll
                for (int j = 0; j < 8; j++) acc[i][j] += a[i] * bb[j];
        }
        __syncthreads();
    }
#pragma unroll
    for (int i = 0; i < 8; i++) {
        int row = (i < 4) ? ty*4 + i : 64 + ty*4 + (i-4);
        float4 v0 = make_float4(acc[i][0], acc[i][1], acc[i][2], acc[i][3]);
        float4 v1 = make_float4(acc[i][4], acc[i][5], acc[i][6], acc[i][7]);
        *(float4*)&d_xd[(size_t)(row0+row)*NC + ch*128 + tx*4]      = v0;
        *(float4*)&d_xd[(size_t)(row0+row)*NC + ch*128 + 64 + tx*4] = v1;
    }
}

// SpMM scatter
__global__ void k_spmm(const int* __restrict__ rows, const int* __restrict__ cols,
                       const float* __restrict__ vals, int which) {
    int tid = threadIdx.x;
    int e = blockIdx.x * 4 + (tid >> 6);
    int c = (tid & 63) * 4;
    int r  = rows[e];
    int cl = cols[e];
    float v = vals[e];
    float* out = which ? d_gY : d_gX;
    float4 s = *(const float4*)&d_xd[(size_t)cl * NC + c];
    float* o = out + (size_t)r * NC + c;
    atomicAdd(o + 0, v * s.x);
    atomicAdd(o + 1, v * s.y);
    atomicAdd(o + 2, v * s.z);
    atomicAdd(o + 3, v * s.w);
}

// ========================== B-operand prep (bf16 split) ======================
__global__ void k_prep_cplxB(const float* __restrict__ Are, const float* __restrict__ Aim) {
    int i = blockIdx.x * 256 + threadIdx.x;   // < 262144
    int n = i >> 9, k = i & 511;
    float v;
    if (n < 256) v = (k < 256) ? Are[n*256 + k] : -Aim[n*256 + (k-256)];
    else {
        int n2 = n - 256;
        v = (k < 256) ? Aim[n2*256 + k] : Are[n2*256 + (k-256)];
    }
    split_store(v, &d_Bh[BOFF_CPLX + i], &d_Bl[BOFF_CPLX + i]);
}

__global__ void k_prep_wT(const float* __restrict__ W, int K, int N, int off) {
    int i = blockIdx.x * 256 + threadIdx.x;
    if (i >= N * K) return;
    int n = i / K, k = i % K;
    split_store(W[k*N + n], &d_Bh[off + i], &d_Bl[off + i]);
}

// ========================= activation splits ================================
__global__ void k_split_gxy() {
    int tid = threadIdx.x;
    size_t i = (size_t)(blockIdx.x * 256 + tid) * 4;
    size_t row = i >> 8; int c = (int)(i & 255);
    float4 gx = *(float4*)&d_gX[i];
    float4 gy = *(float4*)&d_gY[i];
    size_t base = row * 768;
#pragma unroll
    for (int j = 0; j < 4; j++) {
        float vx = (&gx.x)[j], vy = (&gy.x)[j];
        split_store(vx, &d_Ah[base + c + j],       &d_Al[base + c + j]);
        split_store(vy, &d_Ah[base + 256 + c + j], &d_Al[base + 256 + c + j]);
    }
}

__global__ void k_tanh_split() {
    int tid = threadIdx.x;
    size_t i = (size_t)(blockIdx.x * 256 + tid) * 4;
    size_t row = i >> 8; int c = (int)(i & 255);
    float4 gx = *(float4*)&d_gX[i];
    float4 gy = *(float4*)&d_gY[i];
    float4 br = *(float4*)&d_bb[row*512 + c];
    float4 bi = *(float4*)&d_bb[row*512 + 256 + c];
    size_t base = row * 768 + 512 + c;
#pragma unroll
    for (int j = 0; j < 4; j++) {
        float v = tanhf((&gx.x)[j] * (&br.x)[j] + (&gy.x)[j] * (&bi.x)[j]);
        split_store(v, &d_Ah[base + j], &d_Al[base + j]);
    }
}

__global__ void k_split_xxd(const float* __restrict__ x) {
    int tid = threadIdx.x;
    size_t i = (size_t)(blockIdx.x * 256 + tid) * 4;
    size_t row = i >> 8; int c = (int)(i & 255);
    float4 xv = *(const float4*)&x[i];
    float4 xd = *(float4*)&d_xd[i];
    size_t base = row * 768;
#pragma unroll
    for (int j = 0; j < 4; j++) {
        split_store((&xv.x)[j], &d_Ah[base + c + j],       &d_Al[base + c + j]);
        split_store((&xd.x)[j], &d_Ah[base + 256 + c + j], &d_Al[base + 256 + c + j]);
    }
}

__global__ void k_bnsplit(const float* __restrict__ h, int statoff,
                          const float* __restrict__ g, const float* __restrict__ be) {
    int tid = threadIdx.x;
    __shared__ float sc[256], sh[256];
    {
        float mean = d_stats[statoff + tid] * (1.0f / NN);
        float var  = d_stats[statoff + 256 + tid] * (1.0f / NN) - mean * mean;
        float s = rsqrtf(var + BNEPS) * g[tid];
        sc[tid] = s;
        sh[tid] = be[tid] - mean * s;
    }
    __syncthreads();
    size_t i = (size_t)(blockIdx.x * 256 + tid) * 4;
    size_t row = i >> 8; int c = (int)(i & 255);
    float4 hv = *(const float4*)&h[i];
    size_t base = row * 768 + c;
#pragma unroll
    for (int j = 0; j < 4; j++) {
        float v = fmaxf((&hv.x)[j] * sc[c+j] + sh[c+j], 0.f);
        split_store(v, &d_Ah[base + j], &d_Al[base + j]);
    }
}

// ========================= mma.sync bf16-split GEMM ==========================
// out[M,Ntot] = A[M,K] @ B[Ntot,K]^T ; A = Ah+Al, B = Bh+Bl (bf16 split, 3 MMAs)
// grid (M/128, Ntot/128), 256 threads (8 warps: 2 M-slabs x 4 N-slabs).
#define ASTR 40                    // smem row stride (elements), conflict-free
#define TILEEL (128*ASTR)          // 5120 elements = 10240 bytes per matrix
#define GEMM_SMEM (2*4*TILEEL*2)   // 2 stages * 4 matrices * bytes = 81920

__device__ __forceinline__ void ldsm_x4(uint32_t* r, uint32_t addr) {
    asm volatile("ldmatrix.sync.aligned.m8n8.x4.shared.b16 {%0,%1,%2,%3}, [%4];"
                 : "=r"(r[0]), "=r"(r[1]), "=r"(r[2]), "=r"(r[3]) : "r"(addr));
}
__device__ __forceinline__ void ldsm_x2(uint32_t* r, uint32_t addr) {
    asm volatile("ldmatrix.sync.aligned.m8n8.x2.shared.b16 {%0,%1}, [%2];"
                 : "=r"(r[0]), "=r"(r[1]) : "r"(addr));
}
__device__ __forceinline__ void mma16816(float* c, const uint32_t* a, const uint32_t* b) {
    asm volatile("mma.sync.aligned.m16n8k16.row.col.f32.bf16.bf16.f32 "
                 "{%0,%1,%2,%3}, {%4,%5,%6,%7}, {%8,%9}, {%0,%1,%2,%3};"
                 : "+f"(c[0]), "+f"(c[1]), "+f"(c[2]), "+f"(c[3])
                 : "r"(a[0]), "r"(a[1]), "r"(a[2]), "r"(a[3]), "r"(b[0]), "r"(b[1]));
}
#define CP_ASYNC(sm, gm) \
    asm volatile("cp.async.cg.shared.global [%0], [%1], 16;" :: "r"(sm), "l"(gm))
#define CP_COMMIT() asm volatile("cp.async.commit_group;" ::: "memory")
#define CP_WAIT(n)  asm volatile("cp.async.wait_group %0;" :: "n"(n) : "memory")

__global__ __launch_bounds__(256) void k_mma_gemm(
    const __nv_bfloat16* __restrict__ Ah, const __nv_bfloat16* __restrict__ Al, int ldA,
    const __nv_bfloat16* __restrict__ Bh, const __nv_bfloat16* __restrict__ Bl,
    float* __restrict__ out, int ldout, const float* __restrict__ bias, int K)
{
    extern __shared__ __align__(16) __nv_bfloat16 sm[];
    int tid = threadIdx.x;
    int wid = tid >> 5, lane = tid & 31;
    int wm = wid & 1, wn = wid >> 1;
    int row0 = blockIdx.x * 128, n0 = blockIdx.y * 128;

    float acc[4][4][4];
#pragma unroll
    for (int mi = 0; mi < 4; mi++)
#pragma unroll
        for (int ni = 0; ni < 4; ni++)
#pragma unroll
            for (int q = 0; q < 4; q++) acc[mi][ni][q] = 0.f;

    // per-thread load coords (2 x 16B chunks per matrix per stage)
    int idx0 = tid * 2, idx1 = tid * 2 + 1;
    int lr0 = idx0 >> 2, ls0 = idx0 & 3;
    int lr1 = idx1 >> 2, ls1 = idx1 & 3;
    uint32_t so0 = (uint32_t)(lr0 * ASTR + ls0 * 8) * 2;
    uint32_t so1 = (uint32_t)(lr1 * ASTR + ls1 * 8) * 2;
    uint32_t smbase = smem_u32(sm);

    const int S = K >> 5;

#define LOADSTAGE(s) do { \
    int buf = (s) & 1; \
    uint32_t sb = smbase + (uint32_t)buf * 4u * TILEEL * 2u; \
    int k0 = (s) << 5; \
    const __nv_bfloat16* gah0 = Ah + (size_t)(row0 + lr0) * ldA + k0 + ls0*8; \
    const __nv_bfloat16* gah1 = Ah + (size_t)(row0 + lr1) * ldA + k0 + ls1*8; \
    const __nv_bfloat16* gal0 = Al + (size_t)(row0 + lr0) * ldA + k0 + ls0*8; \
    const __nv_bfloat16* gal1 = Al + (size_t)(row0 + lr1) * ldA + k0 + ls1*8; \
    const __nv_bfloat16* gbh0 = Bh + (size_t)(n0 + lr0) * K + k0 + ls0*8; \
    const __nv_bfloat16* gbh1 = Bh + (size_t)(n0 + lr1) * K + k0 + ls1*8; \
    const __nv_bfloat16* gbl0 = Bl + (size_t)(n0 + lr0) * K + k0 + ls0*8; \
    const __nv_bfloat16* gbl1 = Bl + (size_t)(n0 + lr1) * K + k0 + ls1*8; \
    CP_ASYNC(sb + so0, gah0);                       CP_ASYNC(sb + so1, gah1); \
    CP_ASYNC(sb + TILEEL*2 + so0, gal0);            CP_ASYNC(sb + TILEEL*2 + so1, gal1); \
    CP_ASYNC(sb + 2*TILEEL*2 + so0, gbh0);          CP_ASYNC(sb + 2*TILEEL*2 + so1, gbh1); \
    CP_ASYNC(sb + 3*TILEEL*2 + so0, gbl0);          CP_ASYNC(sb + 3*TILEEL*2 + so1, gbl1); \
} while (0)

    LOADSTAGE(0);
    CP_COMMIT();

    int arow = (lane & 15);
    int acol = (lane >> 4) * 8;
    int brow = (lane & 7);
    int bcol = ((lane >> 3) & 1) * 8;

    for (int s = 0; s < S; s++) {
        if (s + 1 < S) { LOADSTAGE(s + 1); CP_COMMIT(); CP_WAIT(1); }
        else           { CP_WAIT(0); }
        __syncthreads();

        uint32_t sb = smbase + (uint32_t)(s & 1) * 4u * TILEEL * 2u;
        uint32_t Ah_s = sb;
        uint32_t Al_s = sb + TILEEL * 2;
        uint32_t Bh_s = sb + 2 * TILEEL * 2;
        uint32_t Bl_s = sb + 3 * TILEEL * 2;

#pragma unroll
        for (int ks = 0; ks < 2; ks++) {
            int k0 = ks * 16;
            uint32_t aH[4][4], aL[4][4];
#pragma unroll
            for (int mi = 0; mi < 4; mi++) {
                uint32_t off = (uint32_t)((wm*64 + mi*16 + arow) * ASTR + k0 + acol) * 2;
                ldsm_x4(aH[mi], Ah_s + off);
                ldsm_x4(aL[mi], Al_s + off);
            }
            uint32_t bH[4][2], bL[4][2];
#pragma unroll
            for (int ni = 0; ni < 4; ni++) {
                uint32_t off = (uint32_t)((wn*32 + ni*8 + brow) * ASTR + k0 + bcol) * 2;
                ldsm_x2(bH[ni], Bh_s + off);
                ldsm_x2(bL[ni], Bl_s + off);
            }
#pragma unroll
            for (int mi = 0; mi < 4; mi++)
#pragma unroll
                for (int ni = 0; ni < 4; ni++) {
                    mma16816(acc[mi][ni], aH[mi], bH[ni]);
                    mma16816(acc[mi][ni], aH[mi], bL[ni]);
                    mma16816(acc[mi][ni], aL[mi], bH[ni]);
                }
        }
        __syncthreads();
    }

    // epilogue
    int g4 = lane >> 2, t4 = lane & 3;
#pragma unroll
    for (int mi = 0; mi < 4; mi++) {
        int r = row0 + wm*64 + mi*16 + g4;
#pragma unroll
        for (int ni = 0; ni < 4; ni++) {
            int c = n0 + wn*32 + ni*8 + t4*2;
            float b0 = 0.f, b1 = 0.f;
            if (bias) { b0 = bias[c]; b1 = bias[c+1]; }
            float2 v0 = make_float2(acc[mi][ni][0] + b0, acc[mi][ni][1] + b1);
            float2 v1 = make_float2(acc[mi][ni][2] + b0, acc[mi][ni][3] + b1);
            *(float2*)&out[(size_t)r * ldout + c]       = v0;
            *(float2*)&out[(size_t)(r+8) * ldout + c]   = v1;
        }
    }
}

// column sum & sumsq
__global__ void k_stats(int stage) {
    const float* M = (stage == 0) ? d_h0 : (stage == 1) ? d_h1 : d_h2;
    float* sums = d_stats + stage * 512;
    float* sqs  = sums + 256;
    int c = threadIdx.x;
    int r0 = blockIdx.x * 256;
    float s = 0.f, q = 0.f;
    for (int r = 0; r < 256; r++) {
        float v = M[(size_t)(r0 + r) * NC + c];
        s += v;
        q += v * v;
    }
    atomicAdd(&sums[c], s);
    atomicAdd(&sqs[c],  q);
}

// out = bn(h2) + x
__global__ void k_final(const float* __restrict__ x, const float* __restrict__ g,
                        const float* __restrict__ be, float* __restrict__ out) {
    int tid = threadIdx.x;
    __shared__ float sc[256], sh[256];
    {
        float mean = d_stats[1024 + tid] * (1.0f / NN);
        float var  = d_stats[1280 + tid] * (1.0f / NN) - mean * mean;
        float s = rsqrtf(var + BNEPS) * g[tid];
        sc[tid] = s;
        sh[tid] = be[tid] - mean * s;
    }
    __syncthreads();
    size_t i = (size_t)(blockIdx.x * 256 + tid) * 4;
    int c = (int)(i & 255);
    float4 h  = *(float4*)&d_h2[i];
    float4 xv = *(const float4*)&x[i];
    float4 o;
    o.x = h.x * sc[c+0] + sh[c+0] + xv.x;
    o.y = h.y * sc[c+1] + sh[c+1] + xv.y;
    o.z = h.z * sc[c+2] + sh[c+2] + xv.z;
    o.w = h.w * sc[c+3] + sh[c+3] + xv.w;
    *(float4*)&out[i] = o;
}

// ------------------------------- launch --------------------------------------
extern "C" void kernel_launch(void* const* d_in, const int* in_sizes, int n_in,
                              void* d_out, int out_size) {
    const float* x       = (const float*)d_in[0];
    const float* mass    = (const float*)d_in[1];
    const float* evals   = (const float*)d_in[2];
    const float* evecs   = (const float*)d_in[3];
    const int*   gx_rows = (const int*)  d_in[4];
    const int*   gx_cols = (const int*)  d_in[5];
    const float* gx_vals = (const float*)d_in[6];
    const int*   gy_rows = (const int*)  d_in[7];
    const int*   gy_cols = (const int*)  d_in[8];
    const float* gy_vals = (const float*)d_in[9];
    const float* dt      = (const float*)d_in[10];
    const float* A_re    = (const float*)d_in[11];
    const float* A_im    = (const float*)d_in[12];
    const float* W0      = (const float*)d_in[13];
    const float* b0      = (const float*)d_in[14];
    const float* g0      = (const float*)d_in[15];
    const float* be0     = (const float*)d_in[16];
    const float* W1      = (const float*)d_in[17];
    const float* b1      = (const float*)d_in[18];
    const float* g1      = (const float*)d_in[19];
    const float* be1     = (const float*)d_in[20];
    const float* W2      = (const float*)d_in[21];
    const float* b2      = (const float*)d_in[22];
    const float* g2      = (const float*)d_in[23];
    const float* be2     = (const float*)d_in[24];
    float* out = (float*)d_out;

    static int smem_set = 0;
    if (!smem_set) {
        cudaFuncSetAttribute(k_mma_gemm, cudaFuncAttributeMaxDynamicSharedMemorySize, GEMM_SMEM);
        smem_set = 1;
    }

    __nv_bfloat16 *Ah, *Al, *Bh, *Bl;
    float *bb, *h0, *h1, *h2;
    cudaGetSymbolAddress((void**)&Ah, d_Ah);
    cudaGetSymbolAddress((void**)&Al, d_Al);
    cudaGetSymbolAddress((void**)&Bh, d_Bh);
    cudaGetSymbolAddress((void**)&Bl, d_Bl);
    cudaGetSymbolAddress((void**)&bb, d_bb);
    cudaGetSymbolAddress((void**)&h0, d_h0);
    cudaGetSymbolAddress((void**)&h1, d_h1);
    cudaGetSymbolAddress((void**)&h2, d_h2);

    k_zero<<<16384, 256>>>();
    k_xspec<<<dim3(16, 2, 8), 256>>>(x, mass, evecs);
    k_coef<<<1024, 256>>>(evals, dt);
    k_xdiff<<<dim3(64, 2, 8), 256>>>(evecs);
    k_spmm<<<NNZ/4, 256>>>(gx_rows, gx_cols, gx_vals, 0);
    k_spmm<<<NNZ/4, 256>>>(gy_rows, gy_cols, gy_vals, 1);

    // weight prep (small)
    k_prep_cplxB<<<1024, 256>>>(A_re, A_im);
    k_prep_wT<<<768, 256>>>(W0, 768, 256, BOFF_W0);
    k_prep_wT<<<256, 256>>>(W1, 256, 256, BOFF_W1);
    k_prep_wT<<<256, 256>>>(W2, 256, 256, BOFF_W2);

    // complex gradient GEMM: [bre|bim] = [gX|gY] @ B'^T
    k_split_gxy<<<16384, 256>>>();
    k_mma_gemm<<<dim3(512, 4), 256, GEMM_SMEM>>>(Ah, Al, 768, Bh + BOFF_CPLX, Bl + BOFF_CPLX,
                                                 bb, 512, nullptr, 512);
    k_tanh_split<<<16384, 256>>>();
    k_split_xxd<<<16384, 256>>>(x);

    // MLP
    k_mma_gemm<<<dim3(512, 2), 256, GEMM_SMEM>>>(Ah, Al, 768, Bh + BOFF_W0, Bl + BOFF_W0,
                                                 h0, 256, b0, 768);
    k_stats<<<256, 256>>>(0);
    k_bnsplit<<<16384, 256>>>(h0, 0, g0, be0);
    k_mma_gemm<<<dim3(512, 2), 256, GEMM_SMEM>>>(Ah, Al, 768, Bh + BOFF_W1, Bl + BOFF_W1,
                                                 h1, 256, b1, 256);
    k_stats<<<256, 256>>>(1);
    k_bnsplit<<<16384, 256>>>(h1, 512, g1, be1);
    k_mma_gemm<<<dim3(512, 2), 256, GEMM_SMEM>>>(Ah, Al, 768, Bh + BOFF_W2, Bl + BOFF_W2,
                                                 h2, 256, b2, 256);
    k_stats<<<256, 256>>>(2);
    k_final<<<16384, 256>>>(x, g2, be2, out);
}

// round 4
// speedup vs baseline: 1.8237x; 1.3755x over previous
#include <cuda_runtime.h>
#include <cuda_bf16.h>
#include <math.h>
#include <cstdint>

#define NB 8
#define NV 8192
#define NK 128
#define NC 256
#define NN 65536          // NB*NV
#define NNZ 1048576       // 16*NN
#define BNEPS 1e-5f

// ------------------------- scratch (device globals) -------------------------
static __device__ float d_xspec[NB*NK*NC];
static __device__ float d_y   [NB*NK*NC];
static __device__ float d_xd  [NN*NC];
static __device__ float d_gX  [NN*NC];
static __device__ float d_gY  [NN*NC];
static __device__ float d_bb  [(size_t)NN*512];  // [bre | bim]
static __device__ float d_h0  [NN*NC];
static __device__ float d_h1  [NN*NC];
static __device__ float d_h2  [NN*NC];
static __device__ float d_stats[1536];
// bf16 split A: [NN, 768] hi/lo
static __device__ __nv_bfloat16 d_Ah[(size_t)NN*768];
static __device__ __nv_bfloat16 d_Al[(size_t)NN*768];
// bf16 split B pool: cplx(512x512) | W0T(256x768) | W1T(256x256) | W2T(256x256)
#define BOFF_CPLX 0
#define BOFF_W0   262144
#define BOFF_W1   458752
#define BOFF_W2   524288
static __device__ __nv_bfloat16 d_Bh[589824];
static __device__ __nv_bfloat16 d_Bl[589824];

__device__ __forceinline__ void split_store(float v, __nv_bfloat16* ph, __nv_bfloat16* pl) {
    __nv_bfloat16 h = __float2bfloat16(v);
    *ph = h;
    *pl = __float2bfloat16(v - __bfloat162float(h));
}

__device__ __forceinline__ uint32_t smem_u32(const void* p) {
    uint32_t a;
    asm("{ .reg .u64 t; cvta.to.shared.u64 t, %1; cvt.u32.u64 %0, t; }" : "=r"(a) : "l"(p));
    return a;
}

// ------------------------------- zero init ----------------------------------
__global__ void k_zero() {
    int i = (blockIdx.x * 256 + threadIdx.x) * 4;
    float4 z = make_float4(0.f, 0.f, 0.f, 0.f);
    *(float4*)&d_gX[i] = z;
    *(float4*)&d_gY[i] = z;
    if (i < NB*NK*NC) *(float4*)&d_xspec[i] = z;
    if (i < 1536)     *(float4*)&d_stats[i] = z;
}

// ---------------------------------------------------------------------------
// x_spec[b,k,c] = sum_v mass[b,v]*evecs[b,v,k]*x[b,v,c]   grid (16,2,8)
// ---------------------------------------------------------------------------
__global__ __launch_bounds__(256) void k_xspec(
    const float* __restrict__ x, const float* __restrict__ mass,
    const float* __restrict__ evecs)
{
    int vc = blockIdx.x, ch = blockIdx.y, b = blockIdx.z;
    int v0 = vc * 512;
    int tid = threadIdx.x;
    int tx = tid & 15, ty = tid >> 4;

    __shared__ __align__(16) float As[8][136];
    __shared__ __align__(16) float Bs[8][136];

    float acc[8][8];
#pragma unroll
    for (int i = 0; i < 8; i++)
#pragma unroll
        for (int j = 0; j < 8; j++) acc[i][j] = 0.f;

    const float* evb = evecs + (size_t)(b*NV + v0) * NK;
    const float* xb  = x     + (size_t)(b*NV + v0) * NC + ch*128;
    const float* mb  = mass + b*NV + v0;

    for (int vs = 0; vs < 512; vs += 8) {
#pragma unroll
        for (int i = 0; i < 4; i++) {
            int e = tid + i*256;
            int vv = e >> 7, kx = e & 127;
            As[vv][kx] = evb[(size_t)(vs+vv)*NK + kx] * mb[vs+vv];
        }
#pragma unroll
        for (int i = 0; i < 4; i++) {
            int e = tid + i*256;
            int vv = e >> 7, c = e & 127;
            Bs[vv][c] = xb[(size_t)(vs+vv)*NC + c];
        }
        __syncthreads();
#pragma unroll
        for (int kk = 0; kk < 8; kk++) {
            float a[8], bb[8];
            *(float4*)(a)    = *(const float4*)&As[kk][ty*4];
            *(float4*)(a+4)  = *(const float4*)&As[kk][64 + ty*4];
            *(float4*)(bb)   = *(const float4*)&Bs[kk][tx*4];
            *(float4*)(bb+4) = *(const float4*)&Bs[kk][64 + tx*4];
#pragma unroll
            for (int i = 0; i < 8; i++)
#pragma unroll
                for (int j = 0; j < 8; j++) acc[i][j] += a[i] * bb[j];
        }
        __syncthreads();
    }
#pragma unroll
    for (int i = 0; i < 8; i++) {
        int kr = (i < 4) ? ty*4 + i : 64 + ty*4 + (i-4);
#pragma unroll
        for (int j = 0; j < 8; j++) {
            int c = (j < 4) ? tx*4 + j : 64 + tx*4 + (j-4);
            atomicAdd(&d_xspec[(b*NK + kr)*NC + ch*128 + c], acc[i][j]);
        }
    }
}

__global__ void k_coef(const float* __restrict__ evals, const float* __restrict__ dt) {
    int i = blockIdx.x * 256 + threadIdx.x;
    int c = i & 255;
    int bk = i >> 8;
    float t = fmaxf(dt[c], 1e-8f);
    d_y[i] = expf(-evals[bk] * t) * d_xspec[i];
}

// x_diffuse = evecs @ y   grid (64, 2, 8)
__global__ __launch_bounds__(256) void k_xdiff(const float* __restrict__ evecs) {
    int rb = blockIdx.x, ch = blockIdx.y, b = blockIdx.z;
    int tid = threadIdx.x;
    int tx = tid & 15, ty = tid >> 4;

    __shared__ __align__(16) float As[8][136];
    __shared__ __align__(16) float Bs[8][136];

    float acc[8][8];
#pragma unroll
    for (int i = 0; i < 8; i++)
#pragma unroll
        for (int j = 0; j < 8; j++) acc[i][j] = 0.f;

    int row0 = b*NV + rb*128;
    int r = tid >> 1, kq = (tid & 1) * 4;
    const float* yB = d_y + b*NK*NC + ch*128;

    for (int k0 = 0; k0 < NK; k0 += 8) {
        float4 av = *(const float4*)&evecs[(size_t)(row0 + r)*NK + k0 + kq];
        As[kq+0][r] = av.x; As[kq+1][r] = av.y; As[kq+2][r] = av.z; As[kq+3][r] = av.w;
#pragma unroll
        for (int i = 0; i < 4; i++) {
            int e = tid + i*256;
            int kk = e >> 7, c = e & 127;
            Bs[kk][c] = yB[(k0+kk)*NC + c];
        }
        __syncthreads();
#pragma unroll
        for (int kk = 0; kk < 8; kk++) {
            float a[8], bb[8];
            *(float4*)(a)    = *(const float4*)&As[kk][ty*4];
            *(float4*)(a+4)  = *(const float4*)&As[kk][64 + ty*4];
            *(float4*)(bb)   = *(const float4*)&Bs[kk][tx*4];
            *(float4*)(bb+4) = *(const float4*)&Bs[kk][64 + tx*4];
#pragma unroll
            for (int i = 0; i < 8; i++)
#pragma unroll
                for (int j = 0; j < 8; j++) acc[i][j] += a[i] * bb[j];
        }
        __syncthreads();
    }
#pragma unroll
    for (int i = 0; i < 8; i++) {
        int row = (i < 4) ? ty*4 + i : 64 + ty*4 + (i-4);
        float4 v0 = make_float4(acc[i][0], acc[i][1], acc[i][2], acc[i][3]);
        float4 v1 = make_float4(acc[i][4], acc[i][5], acc[i][6], acc[i][7]);
        *(float4*)&d_xd[(size_t)(row0+row)*NC + ch*128 + tx*4]      = v0;
        *(float4*)&d_xd[(size_t)(row0+row)*NC + ch*128 + 64 + tx*4] = v1;
    }
}

// SpMM scatter with 16B vector reductions
__global__ void k_spmm(const int* __restrict__ rows, const int* __restrict__ cols,
                       const float* __restrict__ vals, int which) {
    int tid = threadIdx.x;
    int e = blockIdx.x * 4 + (tid >> 6);
    int c = (tid & 63) * 4;
    int r  = rows[e];
    int cl = cols[e];
    float v = vals[e];
    float* out = which ? d_gY : d_gX;
    float4 s = *(const float4*)&d_xd[(size_t)cl * NC + c];
    float* o = out + (size_t)r * NC + c;
    asm volatile("red.global.add.v4.f32 [%0], {%1,%2,%3,%4};"
                 :: "l"(o), "f"(v*s.x), "f"(v*s.y), "f"(v*s.z), "f"(v*s.w) : "memory");
}

// ========================== B-operand prep (bf16 split) ======================
__global__ void k_prep_cplxB(const float* __restrict__ Are, const float* __restrict__ Aim) {
    int i = blockIdx.x * 256 + threadIdx.x;   // < 262144
    int n = i >> 9, k = i & 511;
    float v;
    if (n < 256) v = (k < 256) ? Are[n*256 + k] : -Aim[n*256 + (k-256)];
    else {
        int n2 = n - 256;
        v = (k < 256) ? Aim[n2*256 + k] : Are[n2*256 + (k-256)];
    }
    split_store(v, &d_Bh[BOFF_CPLX + i], &d_Bl[BOFF_CPLX + i]);
}

__global__ void k_prep_wT(const float* __restrict__ W, int K, int N, int off) {
    int i = blockIdx.x * 256 + threadIdx.x;
    if (i >= N * K) return;
    int n = i / K, k = i % K;
    split_store(W[k*N + n], &d_Bh[off + i], &d_Bl[off + i]);
}

// ========================= activation splits ================================
// pre-cplx: A cols [0..511] = [gX | gY]
__global__ void k_split_gxy() {
    int tid = threadIdx.x;
    size_t i = (size_t)(blockIdx.x * 256 + tid) * 4;
    size_t row = i >> 8; int c = (int)(i & 255);
    float4 gx = *(float4*)&d_gX[i];
    float4 gy = *(float4*)&d_gY[i];
    size_t base = row * 768;
#pragma unroll
    for (int j = 0; j < 4; j++) {
        float vx = (&gx.x)[j], vy = (&gy.x)[j];
        split_store(vx, &d_Ah[base + c + j],       &d_Al[base + c + j]);
        split_store(vy, &d_Ah[base + 256 + c + j], &d_Al[base + 256 + c + j]);
    }
}

// post-cplx merged: cols [0..255]=x, [256..511]=xd, [512..767]=tanh(gX*bre+gY*bim)
__global__ void k_split2(const float* __restrict__ x) {
    int tid = threadIdx.x;
    size_t i = (size_t)(blockIdx.x * 256 + tid) * 4;
    size_t row = i >> 8; int c = (int)(i & 255);
    float4 xv = *(const float4*)&x[i];
    float4 xd = *(float4*)&d_xd[i];
    float4 gx = *(float4*)&d_gX[i];
    float4 gy = *(float4*)&d_gY[i];
    float4 br = *(float4*)&d_bb[row*512 + c];
    float4 bi = *(float4*)&d_bb[row*512 + 256 + c];
    size_t base = row * 768;
#pragma unroll
    for (int j = 0; j < 4; j++) {
        split_store((&xv.x)[j], &d_Ah[base + c + j],       &d_Al[base + c + j]);
        split_store((&xd.x)[j], &d_Ah[base + 256 + c + j], &d_Al[base + 256 + c + j]);
        float v = tanhf((&gx.x)[j] * (&br.x)[j] + (&gy.x)[j] * (&bi.x)[j]);
        split_store(v, &d_Ah[base + 512 + c + j], &d_Al[base + 512 + c + j]);
    }
}

// relu(bn(h)) -> A cols [0..255]
__global__ void k_bnsplit(const float* __restrict__ h, int statoff,
                          const float* __restrict__ g, const float* __restrict__ be) {
    int tid = threadIdx.x;
    __shared__ float sc[256], sh[256];
    {
        float mean = d_stats[statoff + tid] * (1.0f / NN);
        float var  = d_stats[statoff + 256 + tid] * (1.0f / NN) - mean * mean;
        float s = rsqrtf(var + BNEPS) * g[tid];
        sc[tid] = s;
        sh[tid] = be[tid] - mean * s;
    }
    __syncthreads();
    size_t i = (size_t)(blockIdx.x * 256 + tid) * 4;
    size_t row = i >> 8; int c = (int)(i & 255);
    float4 hv = *(const float4*)&h[i];
    size_t base = row * 768 + c;
#pragma unroll
    for (int j = 0; j < 4; j++) {
        float v = fmaxf((&hv.x)[j] * sc[c+j] + sh[c+j], 0.f);
        split_store(v, &d_Ah[base + j], &d_Al[base + j]);
    }
}

// ========================= mma.sync bf16-split GEMM ==========================
// out[M,Ntot] = A[M,K] @ B[Ntot,K]^T ; A = Ah+Al, B = Bh+Bl (bf16 split, 3 MMAs)
// grid (M/128, Ntot/128), 256 threads (8 warps: 2 M-slabs x 4 N-slabs).
// Optionally accumulates per-column sum/sumsq of (out+bias) into stats[0..255/256..511].
#define ASTR 40
#define TILEEL (128*ASTR)
#define GEMM_SMEM (2*4*TILEEL*2)   // 81920

__device__ __forceinline__ void ldsm_x4(uint32_t* r, uint32_t addr) {
    asm volatile("ldmatrix.sync.aligned.m8n8.x4.shared.b16 {%0,%1,%2,%3}, [%4];"
                 : "=r"(r[0]), "=r"(r[1]), "=r"(r[2]), "=r"(r[3]) : "r"(addr));
}
__device__ __forceinline__ void ldsm_x2(uint32_t* r, uint32_t addr) {
    asm volatile("ldmatrix.sync.aligned.m8n8.x2.shared.b16 {%0,%1}, [%2];"
                 : "=r"(r[0]), "=r"(r[1]) : "r"(addr));
}
__device__ __forceinline__ void mma16816(float* c, const uint32_t* a, const uint32_t* b) {
    asm volatile("mma.sync.aligned.m16n8k16.row.col.f32.bf16.bf16.f32 "
                 "{%0,%1,%2,%3}, {%4,%5,%6,%7}, {%8,%9}, {%0,%1,%2,%3};"
                 : "+f"(c[0]), "+f"(c[1]), "+f"(c[2]), "+f"(c[3])
                 : "r"(a[0]), "r"(a[1]), "r"(a[2]), "r"(a[3]), "r"(b[0]), "r"(b[1]));
}
#define CP_ASYNC(sm, gm) \
    asm volatile("cp.async.cg.shared.global [%0], [%1], 16;" :: "r"(sm), "l"(gm))
#define CP_COMMIT() asm volatile("cp.async.commit_group;" ::: "memory")
#define CP_WAIT(n)  asm volatile("cp.async.wait_group %0;" :: "n"(n) : "memory")

__global__ __launch_bounds__(256) void k_mma_gemm(
    const __nv_bfloat16* __restrict__ Ah, const __nv_bfloat16* __restrict__ Al, int ldA,
    const __nv_bfloat16* __restrict__ Bh, const __nv_bfloat16* __restrict__ Bl,
    float* __restrict__ out, int ldout, const float* __restrict__ bias, int K,
    float* __restrict__ stats)
{
    extern __shared__ __align__(16) __nv_bfloat16 sm[];
    int tid = threadIdx.x;
    int wid = tid >> 5, lane = tid & 31;
    int wm = wid & 1, wn = wid >> 1;
    int row0 = blockIdx.x * 128, n0 = blockIdx.y * 128;

    float acc[4][4][4];
#pragma unroll
    for (int mi = 0; mi < 4; mi++)
#pragma unroll
        for (int ni = 0; ni < 4; ni++)
#pragma unroll
            for (int q = 0; q < 4; q++) acc[mi][ni][q] = 0.f;

    int idx0 = tid * 2, idx1 = tid * 2 + 1;
    int lr0 = idx0 >> 2, ls0 = idx0 & 3;
    int lr1 = idx1 >> 2, ls1 = idx1 & 3;
    uint32_t so0 = (uint32_t)(lr0 * ASTR + ls0 * 8) * 2;
    uint32_t so1 = (uint32_t)(lr1 * ASTR + ls1 * 8) * 2;
    uint32_t smbase = smem_u32(sm);

    const int S = K >> 5;

#define LOADSTAGE(s) do { \
    int buf = (s) & 1; \
    uint32_t sb = smbase + (uint32_t)buf * 4u * TILEEL * 2u; \
    int k0 = (s) << 5; \
    const __nv_bfloat16* gah0 = Ah + (size_t)(row0 + lr0) * ldA + k0 + ls0*8; \
    const __nv_bfloat16* gah1 = Ah + (size_t)(row0 + lr1) * ldA + k0 + ls1*8; \
    const __nv_bfloat16* gal0 = Al + (size_t)(row0 + lr0) * ldA + k0 + ls0*8; \
    const __nv_bfloat16* gal1 = Al + (size_t)(row0 + lr1) * ldA + k0 + ls1*8; \
    const __nv_bfloat16* gbh0 = Bh + (size_t)(n0 + lr0) * K + k0 + ls0*8; \
    const __nv_bfloat16* gbh1 = Bh + (size_t)(n0 + lr1) * K + k0 + ls1*8; \
    const __nv_bfloat16* gbl0 = Bl + (size_t)(n0 + lr0) * K + k0 + ls0*8; \
    const __nv_bfloat16* gbl1 = Bl + (size_t)(n0 + lr1) * K + k0 + ls1*8; \
    CP_ASYNC(sb + so0, gah0);                       CP_ASYNC(sb + so1, gah1); \
    CP_ASYNC(sb + TILEEL*2 + so0, gal0);            CP_ASYNC(sb + TILEEL*2 + so1, gal1); \
    CP_ASYNC(sb + 2*TILEEL*2 + so0, gbh0);          CP_ASYNC(sb + 2*TILEEL*2 + so1, gbh1); \
    CP_ASYNC(sb + 3*TILEEL*2 + so0, gbl0);          CP_ASYNC(sb + 3*TILEEL*2 + so1, gbl1); \
} while (0)

    LOADSTAGE(0);
    CP_COMMIT();

    int arow = (lane & 15);
    int acol = (lane >> 4) * 8;
    int brow = (lane & 7);
    int bcol = ((lane >> 3) & 1) * 8;

    for (int s = 0; s < S; s++) {
        if (s + 1 < S) { LOADSTAGE(s + 1); CP_COMMIT(); CP_WAIT(1); }
        else           { CP_WAIT(0); }
        __syncthreads();

        uint32_t sb = smbase + (uint32_t)(s & 1) * 4u * TILEEL * 2u;
        uint32_t Ah_s = sb;
        uint32_t Al_s = sb + TILEEL * 2;
        uint32_t Bh_s = sb + 2 * TILEEL * 2;
        uint32_t Bl_s = sb + 3 * TILEEL * 2;

#pragma unroll
        for (int ks = 0; ks < 2; ks++) {
            int k0 = ks * 16;
            uint32_t aH[4][4], aL[4][4];
#pragma unroll
            for (int mi = 0; mi < 4; mi++) {
                uint32_t off = (uint32_t)((wm*64 + mi*16 + arow) * ASTR + k0 + acol) * 2;
                ldsm_x4(aH[mi], Ah_s + off);
                ldsm_x4(aL[mi], Al_s + off);
            }
            uint32_t bH[4][2], bL[4][2];
#pragma unroll
            for (int ni = 0; ni < 4; ni++) {
                uint32_t off = (uint32_t)((wn*32 + ni*8 + brow) * ASTR + k0 + bcol) * 2;
                ldsm_x2(bH[ni], Bh_s + off);
                ldsm_x2(bL[ni], Bl_s + off);
            }
#pragma unroll
            for (int mi = 0; mi < 4; mi++)
#pragma unroll
                for (int ni = 0; ni < 4; ni++) {
                    mma16816(acc[mi][ni], aH[mi], bH[ni]);
                    mma16816(acc[mi][ni], aH[mi], bL[ni]);
                    mma16816(acc[mi][ni], aL[mi], bH[ni]);
                }
        }
        __syncthreads();
    }

    // epilogue (+ optional per-column stats)
    int g4 = lane >> 2, t4 = lane & 3;
    float cs[4][2], cq[4][2];
#pragma unroll
    for (int ni = 0; ni < 4; ni++) { cs[ni][0]=cs[ni][1]=cq[ni][0]=cq[ni][1]=0.f; }

#pragma unroll
    for (int mi = 0; mi < 4; mi++) {
        int r = row0 + wm*64 + mi*16 + g4;
#pragma unroll
        for (int ni = 0; ni < 4; ni++) {
            int c = n0 + wn*32 + ni*8 + t4*2;
            float b0 = 0.f, b1 = 0.f;
            if (bias) { b0 = bias[c]; b1 = bias[c+1]; }
            float v0 = acc[mi][ni][0] + b0, v1 = acc[mi][ni][1] + b1;
            float v2 = acc[mi][ni][2] + b0, v3 = acc[mi][ni][3] + b1;
            *(float2*)&out[(size_t)r * ldout + c]     = make_float2(v0, v1);
            *(float2*)&out[(size_t)(r+8) * ldout + c] = make_float2(v2, v3);
            cs[ni][0] += v0 + v2;  cq[ni][0] += v0*v0 + v2*v2;
            cs[ni][1] += v1 + v3;  cq[ni][1] += v1*v1 + v3*v3;
        }
    }
    if (stats) {
#pragma unroll
        for (int ni = 0; ni < 4; ni++) {
#pragma unroll
            for (int h = 0; h < 2; h++) {
                float s = cs[ni][h], q = cq[ni][h];
                s += __shfl_xor_sync(0xFFFFFFFFu, s, 4);
                q += __shfl_xor_sync(0xFFFFFFFFu, q, 4);
                s += __shfl_xor_sync(0xFFFFFFFFu, s, 8);
                q += __shfl_xor_sync(0xFFFFFFFFu, q, 8);
                s += __shfl_xor_sync(0xFFFFFFFFu, s, 16);
                q += __shfl_xor_sync(0xFFFFFFFFu, q, 16);
                if (g4 == 0) {
                    int c = n0 + wn*32 + ni*8 + t4*2 + h;
                    atomicAdd(&stats[c], s);
                    atomicAdd(&stats[256 + c], q);
                }
            }
        }
    }
}

// out = bn(h2) + x
__global__ void k_final(const float* __restrict__ x, const float* __restrict__ g,
                        const float* __restrict__ be, float* __restrict__ out) {
    int tid = threadIdx.x;
    __shared__ float sc[256], sh[256];
    {
        float mean = d_stats[1024 + tid] * (1.0f / NN);
        float var  = d_stats[1280 + tid] * (1.0f / NN) - mean * mean;
        float s = rsqrtf(var + BNEPS) * g[tid];
        sc[tid] = s;
        sh[tid] = be[tid] - mean * s;
    }
    __syncthreads();
    size_t i = (size_t)(blockIdx.x * 256 + tid) * 4;
    int c = (int)(i & 255);
    float4 h  = *(float4*)&d_h2[i];
    float4 xv = *(const float4*)&x[i];
    float4 o;
    o.x = h.x * sc[c+0] + sh[c+0] + xv.x;
    o.y = h.y * sc[c+1] + sh[c+1] + xv.y;
    o.z = h.z * sc[c+2] + sh[c+2] + xv.z;
    o.w = h.w * sc[c+3] + sh[c+3] + xv.w;
    *(float4*)&out[i] = o;
}

// ------------------------------- launch --------------------------------------
extern "C" void kernel_launch(void* const* d_in, const int* in_sizes, int n_in,
                              void* d_out, int out_size) {
    const float* x       = (const float*)d_in[0];
    const float* mass    = (const float*)d_in[1];
    const float* evals   = (const float*)d_in[2];
    const float* evecs   = (const float*)d_in[3];
    const int*   gx_rows = (const int*)  d_in[4];
    const int*   gx_cols = (const int*)  d_in[5];
    const float* gx_vals = (const float*)d_in[6];
    const int*   gy_rows = (const int*)  d_in[7];
    const int*   gy_cols = (const int*)  d_in[8];
    const float* gy_vals = (const float*)d_in[9];
    const float* dt      = (const float*)d_in[10];
    const float* A_re    = (const float*)d_in[11];
    const float* A_im    = (const float*)d_in[12];
    const float* W0      = (const float*)d_in[13];
    const float* b0      = (const float*)d_in[14];
    const float* g0      = (const float*)d_in[15];
    const float* be0     = (const float*)d_in[16];
    const float* W1      = (const float*)d_in[17];
    const float* b1      = (const float*)d_in[18];
    const float* g1      = (const float*)d_in[19];
    const float* be1     = (const float*)d_in[20];
    const float* W2      = (const float*)d_in[21];
    const float* b2      = (const float*)d_in[22];
    const float* g2      = (const float*)d_in[23];
    const float* be2     = (const float*)d_in[24];
    float* out = (float*)d_out;

    static int smem_set = 0;
    if (!smem_set) {
        cudaFuncSetAttribute(k_mma_gemm, cudaFuncAttributeMaxDynamicSharedMemorySize, GEMM_SMEM);
        smem_set = 1;
    }

    __nv_bfloat16 *Ah, *Al, *Bh, *Bl;
    float *bb, *h0, *h1, *h2, *stats;
    cudaGetSymbolAddress((void**)&Ah, d_Ah);
    cudaGetSymbolAddress((void**)&Al, d_Al);
    cudaGetSymbolAddress((void**)&Bh, d_Bh);
    cudaGetSymbolAddress((void**)&Bl, d_Bl);
    cudaGetSymbolAddress((void**)&bb, d_bb);
    cudaGetSymbolAddress((void**)&h0, d_h0);
    cudaGetSymbolAddress((void**)&h1, d_h1);
    cudaGetSymbolAddress((void**)&h2, d_h2);
    cudaGetSymbolAddress((void**)&stats, d_stats);

    k_zero<<<16384, 256>>>();
    k_xspec<<<dim3(16, 2, 8), 256>>>(x, mass, evecs);
    k_coef<<<1024, 256>>>(evals, dt);
    k_xdiff<<<dim3(64, 2, 8), 256>>>(evecs);
    k_spmm<<<NNZ/4, 256>>>(gx_rows, gx_cols, gx_vals, 0);
    k_spmm<<<NNZ/4, 256>>>(gy_rows, gy_cols, gy_vals, 1);

    // weight prep (small)
    k_prep_cplxB<<<1024, 256>>>(A_re, A_im);
    k_prep_wT<<<768, 256>>>(W0, 768, 256, BOFF_W0);
    k_prep_wT<<<256, 256>>>(W1, 256, 256, BOFF_W1);
    k_prep_wT<<<256, 256>>>(W2, 256, 256, BOFF_W2);

    // complex gradient GEMM: [bre|bim] = [gX|gY] @ B'^T
    k_split_gxy<<<16384, 256>>>();
    k_mma_gemm<<<dim3(512, 4), 256, GEMM_SMEM>>>(Ah, Al, 768, Bh + BOFF_CPLX, Bl + BOFF_CPLX,
                                                 bb, 512, nullptr, 512, nullptr);
    k_split2<<<16384, 256>>>(x);

    // MLP (stats fused into epilogues)
    k_mma_gemm<<<dim3(512, 2), 256, GEMM_SMEM>>>(Ah, Al, 768, Bh + BOFF_W0, Bl + BOFF_W0,
                                                 h0, 256, b0, 768, stats);
    k_bnsplit<<<16384, 256>>>(h0, 0, g0, be0);
    k_mma_gemm<<<dim3(512, 2), 256, GEMM_SMEM>>>(Ah, Al, 768, Bh + BOFF_W1, Bl + BOFF_W1,
                                                 h1, 256, b1, 256, stats + 512);
    k_bnsplit<<<16384, 256>>>(h1, 512, g1, be1);
    k_mma_gemm<<<dim3(512, 2), 256, GEMM_SMEM>>>(Ah, Al, 768, Bh + BOFF_W2, Bl + BOFF_W2,
                                                 h2, 256, b2, 256, stats + 1024);
    k_final<<<16384, 256>>>(x, g2, be2, out);
}

// round 5
// speedup vs baseline: 1.8668x; 1.0237x over previous
#include <cuda_runtime.h>
#include <cuda_bf16.h>
#include <math.h>
#include <cstdint>

#define NB 8
#define NV 8192
#define NK 128
#define NC 256
#define NN 65536          // NB*NV
#define NNZ 1048576       // 16*NN
#define BNEPS 1e-5f

// ------------------------- scratch (device globals) -------------------------
static __device__ float d_xspec[NB*NK*NC];
static __device__ float d_xd  [NN*NC];
static __device__ float d_gX  [NN*NC];
static __device__ float d_gY  [NN*NC];
static __device__ float d_bb  [(size_t)NN*512];  // [bre | bim]
static __device__ float d_h0  [NN*NC];
static __device__ float d_h1  [NN*NC];
static __device__ float d_h2  [NN*NC];
static __device__ float d_stats[1536];
// bf16 split A: [NN, 768] hi/lo
static __device__ __nv_bfloat16 d_Ah[(size_t)NN*768];
static __device__ __nv_bfloat16 d_Al[(size_t)NN*768];
// bf16 split B pool: cplx(512x512) | W0T(256x768) | W1T(256x256) | W2T(256x256)
#define BOFF_CPLX 0
#define BOFF_W0   262144
#define BOFF_W1   458752
#define BOFF_W2   524288
static __device__ __nv_bfloat16 d_Bh[589824];
static __device__ __nv_bfloat16 d_Bl[589824];
// spectral operands (bf16 split)
static __device__ __nv_bfloat16 d_mtH[(size_t)NB*NK*NV];   // mevecs^T [b][k][v]
static __device__ __nv_bfloat16 d_mtL[(size_t)NB*NK*NV];
static __device__ __nv_bfloat16 d_xtH[(size_t)NB*NC*NV];   // x^T [b][c][v]
static __device__ __nv_bfloat16 d_xtL[(size_t)NB*NC*NV];
static __device__ __nv_bfloat16 d_eH[(size_t)NN*NK];       // evecs split (row-major)
static __device__ __nv_bfloat16 d_eL[(size_t)NN*NK];
static __device__ __nv_bfloat16 d_ytH[NB*NC*NK];           // (coef*xspec)^T [b][c][k]
static __device__ __nv_bfloat16 d_ytL[NB*NC*NK];

__device__ __forceinline__ void split_store(float v, __nv_bfloat16* ph, __nv_bfloat16* pl) {
    __nv_bfloat16 h = __float2bfloat16(v);
    *ph = h;
    *pl = __float2bfloat16(v - __bfloat162float(h));
}

__device__ __forceinline__ uint32_t smem_u32(const void* p) {
    uint32_t a;
    asm("{ .reg .u64 t; cvta.to.shared.u64 t, %1; cvt.u32.u64 %0, t; }" : "=r"(a) : "l"(p));
    return a;
}

// ------------------------------- zero init ----------------------------------
__global__ void k_zero() {
    int i = (blockIdx.x * 256 + threadIdx.x) * 4;
    float4 z = make_float4(0.f, 0.f, 0.f, 0.f);
    *(float4*)&d_gX[i] = z;
    *(float4*)&d_gY[i] = z;
    if (i < NB*NK*NC) *(float4*)&d_xspec[i] = z;
    if (i < 1536)     *(float4*)&d_stats[i] = z;
}

// ===================== spectral operand preparation ==========================
// mevecs^T: [b][k][v] = evecs[b*V+v][k] * mass[b*V+v].  grid (256, 4, 8), 256 thr
__global__ __launch_bounds__(256) void k_trans_mevecs(
    const float* __restrict__ evecs, const float* __restrict__ mass) {
    __shared__ float tile[32][33];
    int v0 = blockIdx.x * 32, k0 = blockIdx.y * 32, b = blockIdx.z;
    int tx = threadIdx.x & 31, ty = threadIdx.x >> 5;
#pragma unroll
    for (int i = 0; i < 4; i++) {
        int vl = ty + i * 8;
        int gv = b * NV + v0 + vl;
        tile[vl][tx] = evecs[(size_t)gv * NK + k0 + tx] * mass[gv];
    }
    __syncthreads();
#pragma unroll
    for (int i = 0; i < 4; i++) {
        int kl = ty + i * 8;
        size_t o = (size_t)(b * NK + k0 + kl) * NV + v0 + tx;
        split_store(tile[tx][kl], &d_mtH[o], &d_mtL[o]);
    }
}

// x^T: [b][c][v] = x[b*V+v][c].  grid (256, 8, 8), 256 thr
__global__ __launch_bounds__(256) void k_trans_x(const float* __restrict__ x) {
    __shared__ float tile[32][33];
    int v0 = blockIdx.x * 32, c0 = blockIdx.y * 32, b = blockIdx.z;
    int tx = threadIdx.x & 31, ty = threadIdx.x >> 5;
#pragma unroll
    for (int i = 0; i < 4; i++) {
        int vl = ty + i * 8;
        tile[vl][tx] = x[(size_t)(b * NV + v0 + vl) * NC + c0 + tx];
    }
    __syncthreads();
#pragma unroll
    for (int i = 0; i < 4; i++) {
        int cl = ty + i * 8;
        size_t o = (size_t)(b * NC + c0 + cl) * NV + v0 + tx;
        split_store(tile[tx][cl], &d_xtH[o], &d_xtL[o]);
    }
}

// evecs bf16 split (natural layout). grid 8192, 256 thr, 4 elems/thr
__global__ void k_conv_evecs(const float* __restrict__ evecs) {
    size_t i = (size_t)(blockIdx.x * 256 + threadIdx.x) * 4;
    float4 v = *(const float4*)&evecs[i];
#pragma unroll
    for (int j = 0; j < 4; j++)
        split_store((&v.x)[j], &d_eH[i + j], &d_eL[i + j]);
}

// yT[b][c][k] = exp(-evals[b,k]*max(t[c],1e-8)) * xspec[b][k][c]. grid 1024
__global__ void k_coefT(const float* __restrict__ evals, const float* __restrict__ dt) {
    int i = blockIdx.x * 256 + threadIdx.x;   // < 262144
    int c = i & 255, k = (i >> 8) & 127, b = i >> 15;
    float t = fmaxf(dt[c], 1e-8f);
    float v = expf(-evals[b * NK + k] * t) * d_xspec[i];
    int o = b * (NC * NK) + c * NK + k;
    split_store(v, &d_ytH[o], &d_ytL[o]);
}

// ============================ mma primitives =================================
__device__ __forceinline__ void ldsm_x4(uint32_t* r, uint32_t addr) {
    asm volatile("ldmatrix.sync.aligned.m8n8.x4.shared.b16 {%0,%1,%2,%3}, [%4];"
                 : "=r"(r[0]), "=r"(r[1]), "=r"(r[2]), "=r"(r[3]) : "r"(addr));
}
__device__ __forceinline__ void ldsm_x2(uint32_t* r, uint32_t addr) {
    asm volatile("ldmatrix.sync.aligned.m8n8.x2.shared.b16 {%0,%1}, [%2];"
                 : "=r"(r[0]), "=r"(r[1]) : "r"(addr));
}
__device__ __forceinline__ void mma16816(float* c, const uint32_t* a, const uint32_t* b) {
    asm volatile("mma.sync.aligned.m16n8k16.row.col.f32.bf16.bf16.f32 "
                 "{%0,%1,%2,%3}, {%4,%5,%6,%7}, {%8,%9}, {%0,%1,%2,%3};"
                 : "+f"(c[0]), "+f"(c[1]), "+f"(c[2]), "+f"(c[3])
                 : "r"(a[0]), "r"(a[1]), "r"(a[2]), "r"(a[3]), "r"(b[0]), "r"(b[1]));
}
#define CP_ASYNC(sm, gm) \
    asm volatile("cp.async.cg.shared.global [%0], [%1], 16;" :: "r"(sm), "l"(gm))
#define CP_COMMIT() asm volatile("cp.async.commit_group;" ::: "memory")
#define CP_WAIT(n)  asm volatile("cp.async.wait_group %0;" :: "n"(n) : "memory")

#define ASTR 40
#define TILEEL (128*ASTR)
#define GEMM_SMEM (2*4*TILEEL*2)   // 81920

// ------------------- x_spec split-K mma: grid (32, 2, 8) ---------------------
// C[128,128] += mt[b][0:128][kr] @ xt[b][ch*128:+128][kr]^T, red into d_xspec
__global__ __launch_bounds__(256) void k_xspec_mma() {
    extern __shared__ __align__(16) __nv_bfloat16 sm[];
    int tid = threadIdx.x;
    int wid = tid >> 5, lane = tid & 31;
    int wm = wid & 1, wn = wid >> 1;
    int kb = blockIdx.x, ch = blockIdx.y, b = blockIdx.z;
    const __nv_bfloat16* Ah = d_mtH + (size_t)b * NK * NV;
    const __nv_bfloat16* Al = d_mtL + (size_t)b * NK * NV;
    const __nv_bfloat16* Bh = d_xtH + (size_t)(b * NC + ch * 128) * NV;
    const __nv_bfloat16* Bl = d_xtL + (size_t)(b * NC + ch * 128) * NV;
    int kbase = kb * 256;

    float acc[4][4][4];
#pragma unroll
    for (int mi = 0; mi < 4; mi++)
#pragma unroll
        for (int ni = 0; ni < 4; ni++)
#pragma unroll
            for (int q = 0; q < 4; q++) acc[mi][ni][q] = 0.f;

    int idx0 = tid * 2, idx1 = tid * 2 + 1;
    int lr0 = idx0 >> 2, ls0 = idx0 & 3;
    int lr1 = idx1 >> 2, ls1 = idx1 & 3;
    uint32_t so0 = (uint32_t)(lr0 * ASTR + ls0 * 8) * 2;
    uint32_t so1 = (uint32_t)(lr1 * ASTR + ls1 * 8) * 2;
    uint32_t smbase = smem_u32(sm);

#define XLOAD(s) do { \
    uint32_t sb = smbase + (uint32_t)((s) & 1) * 4u * TILEEL * 2u; \
    int k0 = kbase + ((s) << 5); \
    CP_ASYNC(sb + so0, Ah + (size_t)lr0 * NV + k0 + ls0*8); \
    CP_ASYNC(sb + so1, Ah + (size_t)lr1 * NV + k0 + ls1*8); \
    CP_ASYNC(sb + TILEEL*2 + so0, Al + (size_t)lr0 * NV + k0 + ls0*8); \
    CP_ASYNC(sb + TILEEL*2 + so1, Al + (size_t)lr1 * NV + k0 + ls1*8); \
    CP_ASYNC(sb + 2*TILEEL*2 + so0, Bh + (size_t)lr0 * NV + k0 + ls0*8); \
    CP_ASYNC(sb + 2*TILEEL*2 + so1, Bh + (size_t)lr1 * NV + k0 + ls1*8); \
    CP_ASYNC(sb + 3*TILEEL*2 + so0, Bl + (size_t)lr0 * NV + k0 + ls0*8); \
    CP_ASYNC(sb + 3*TILEEL*2 + so1, Bl + (size_t)lr1 * NV + k0 + ls1*8); \
} while (0)

    XLOAD(0);
    CP_COMMIT();

    int arow = (lane & 15), acol = (lane >> 4) * 8;
    int brow = (lane & 7),  bcol = ((lane >> 3) & 1) * 8;

    for (int s = 0; s < 8; s++) {
        if (s + 1 < 8) { XLOAD(s + 1); CP_COMMIT(); CP_WAIT(1); }
        else           { CP_WAIT(0); }
        __syncthreads();
        uint32_t sb = smbase + (uint32_t)(s & 1) * 4u * TILEEL * 2u;
        uint32_t Ah_s = sb, Al_s = sb + TILEEL*2, Bh_s = sb + 2*TILEEL*2, Bl_s = sb + 3*TILEEL*2;
#pragma unroll
        for (int ks = 0; ks < 2; ks++) {
            int k0 = ks * 16;
            uint32_t aH[4][4], aL[4][4];
#pragma unroll
            for (int mi = 0; mi < 4; mi++) {
                uint32_t off = (uint32_t)((wm*64 + mi*16 + arow) * ASTR + k0 + acol) * 2;
                ldsm_x4(aH[mi], Ah_s + off);
                ldsm_x4(aL[mi], Al_s + off);
            }
            uint32_t bH[4][2], bL[4][2];
#pragma unroll
            for (int ni = 0; ni < 4; ni++) {
                uint32_t off = (uint32_t)((wn*32 + ni*8 + brow) * ASTR + k0 + bcol) * 2;
                ldsm_x2(bH[ni], Bh_s + off);
                ldsm_x2(bL[ni], Bl_s + off);
            }
#pragma unroll
            for (int mi = 0; mi < 4; mi++)
#pragma unroll
                for (int ni = 0; ni < 4; ni++) {
                    mma16816(acc[mi][ni], aH[mi], bH[ni]);
                    mma16816(acc[mi][ni], aH[mi], bL[ni]);
                    mma16816(acc[mi][ni], aL[mi], bH[ni]);
                }
        }
        __syncthreads();
    }

    int g4 = lane >> 2, t4 = lane & 3;
#pragma unroll
    for (int mi = 0; mi < 4; mi++) {
        int r = wm*64 + mi*16 + g4;
#pragma unroll
        for (int ni = 0; ni < 4; ni++) {
            int c = ch*128 + wn*32 + ni*8 + t4*2;
            float* o0 = &d_xspec[(b*NK + r) * NC + c];
            float* o1 = &d_xspec[(b*NK + r + 8) * NC + c];
            asm volatile("red.global.add.v2.f32 [%0], {%1,%2};"
                         :: "l"(o0), "f"(acc[mi][ni][0]), "f"(acc[mi][ni][1]) : "memory");
            asm volatile("red.global.add.v2.f32 [%0], {%1,%2};"
                         :: "l"(o1), "f"(acc[mi][ni][2]), "f"(acc[mi][ni][3]) : "memory");
        }
    }
}

// SpMM scatter with 16B vector reductions
__global__ void k_spmm(const int* __restrict__ rows, const int* __restrict__ cols,
                       const float* __restrict__ vals, int which) {
    int tid = threadIdx.x;
    int e = blockIdx.x * 4 + (tid >> 6);
    int c = (tid & 63) * 4;
    int r  = rows[e];
    int cl = cols[e];
    float v = vals[e];
    float* out = which ? d_gY : d_gX;
    float4 s = *(const float4*)&d_xd[(size_t)cl * NC + c];
    float* o = out + (size_t)r * NC + c;
    asm volatile("red.global.add.v4.f32 [%0], {%1,%2,%3,%4};"
                 :: "l"(o), "f"(v*s.x), "f"(v*s.y), "f"(v*s.z), "f"(v*s.w) : "memory");
}

// ========================== B-operand prep (bf16 split) ======================
__global__ void k_prep_cplxB(const float* __restrict__ Are, const float* __restrict__ Aim) {
    int i = blockIdx.x * 256 + threadIdx.x;   // < 262144
    int n = i >> 9, k = i & 511;
    float v;
    if (n < 256) v = (k < 256) ? Are[n*256 + k] : -Aim[n*256 + (k-256)];
    else {
        int n2 = n - 256;
        v = (k < 256) ? Aim[n2*256 + k] : Are[n2*256 + (k-256)];
    }
    split_store(v, &d_Bh[BOFF_CPLX + i], &d_Bl[BOFF_CPLX + i]);
}

__global__ void k_prep_wT(const float* __restrict__ W, int K, int N, int off) {
    int i = blockIdx.x * 256 + threadIdx.x;
    if (i >= N * K) return;
    int n = i / K, k = i % K;
    split_store(W[k*N + n], &d_Bh[off + i], &d_Bl[off + i]);
}

// ========================= activation splits ================================
__global__ void k_split_gxy() {
    int tid = threadIdx.x;
    size_t i = (size_t)(blockIdx.x * 256 + tid) * 4;
    size_t row = i >> 8; int c = (int)(i & 255);
    float4 gx = *(float4*)&d_gX[i];
    float4 gy = *(float4*)&d_gY[i];
    size_t base = row * 768;
#pragma unroll
    for (int j = 0; j < 4; j++) {
        float vx = (&gx.x)[j], vy = (&gy.x)[j];
        split_store(vx, &d_Ah[base + c + j],       &d_Al[base + c + j]);
        split_store(vy, &d_Ah[base + 256 + c + j], &d_Al[base + 256 + c + j]);
    }
}

// post-cplx merged: cols [0..255]=x, [256..511]=xd, [512..767]=tanh(gX*bre+gY*bim)
__global__ void k_split2(const float* __restrict__ x) {
    int tid = threadIdx.x;
    size_t i = (size_t)(blockIdx.x * 256 + tid) * 4;
    size_t row = i >> 8; int c = (int)(i & 255);
    float4 xv = *(const float4*)&x[i];
    float4 xd = *(float4*)&d_xd[i];
    float4 gx = *(float4*)&d_gX[i];
    float4 gy = *(float4*)&d_gY[i];
    float4 br = *(float4*)&d_bb[row*512 + c];
    float4 bi = *(float4*)&d_bb[row*512 + 256 + c];
    size_t base = row * 768;
#pragma unroll
    for (int j = 0; j < 4; j++) {
        split_store((&xv.x)[j], &d_Ah[base + c + j],       &d_Al[base + c + j]);
        split_store((&xd.x)[j], &d_Ah[base + 256 + c + j], &d_Al[base + 256 + c + j]);
        float v = tanhf((&gx.x)[j] * (&br.x)[j] + (&gy.x)[j] * (&bi.x)[j]);
        split_store(v, &d_Ah[base + 512 + c + j], &d_Al[base + 512 + c + j]);
    }
}

// relu(bn(h)) -> A cols [0..255]
__global__ void k_bnsplit(const float* __restrict__ h, int statoff,
                          const float* __restrict__ g, const float* __restrict__ be) {
    int tid = threadIdx.x;
    __shared__ float sc[256], sh[256];
    {
        float mean = d_stats[statoff + tid] * (1.0f / NN);
        float var  = d_stats[statoff + 256 + tid] * (1.0f / NN) - mean * mean;
        float s = rsqrtf(var + BNEPS) * g[tid];
        sc[tid] = s;
        sh[tid] = be[tid] - mean * s;
    }
    __syncthreads();
    size_t i = (size_t)(blockIdx.x * 256 + tid) * 4;
    size_t row = i >> 8; int c = (int)(i & 255);
    float4 hv = *(const float4*)&h[i];
    size_t base = row * 768 + c;
#pragma unroll
    for (int j = 0; j < 4; j++) {
        float v = fmaxf((&hv.x)[j] * sc[c+j] + sh[c+j], 0.f);
        split_store(v, &d_Ah[base + j], &d_Al[base + j]);
    }
}

// ========================= generic mma.sync bf16-split GEMM ==================
__global__ __launch_bounds__(256) void k_mma_gemm(
    const __nv_bfloat16* __restrict__ Ah, const __nv_bfloat16* __restrict__ Al, int ldA,
    const __nv_bfloat16* __restrict__ Bh, const __nv_bfloat16* __restrict__ Bl,
    float* __restrict__ out, int ldout, const float* __restrict__ bias, int K,
    float* __restrict__ stats, int bstrideB)
{
    extern __shared__ __align__(16) __nv_bfloat16 sm[];
    int tid = threadIdx.x;
    int wid = tid >> 5, lane = tid & 31;
    int wm = wid & 1, wn = wid >> 1;
    int row0 = blockIdx.x * 128, n0 = blockIdx.y * 128;
    if (bstrideB) {
        int b = row0 / NV;
        Bh += (size_t)b * bstrideB;
        Bl += (size_t)b * bstrideB;
    }

    float acc[4][4][4];
#pragma unroll
    for (int mi = 0; mi < 4; mi++)
#pragma unroll
        for (int ni = 0; ni < 4; ni++)
#pragma unroll
            for (int q = 0; q < 4; q++) acc[mi][ni][q] = 0.f;

    int idx0 = tid * 2, idx1 = tid * 2 + 1;
    int lr0 = idx0 >> 2, ls0 = idx0 & 3;
    int lr1 = idx1 >> 2, ls1 = idx1 & 3;
    uint32_t so0 = (uint32_t)(lr0 * ASTR + ls0 * 8) * 2;
    uint32_t so1 = (uint32_t)(lr1 * ASTR + ls1 * 8) * 2;
    uint32_t smbase = smem_u32(sm);

    const int S = K >> 5;

#define LOADSTAGE(s) do { \
    int buf = (s) & 1; \
    uint32_t sb = smbase + (uint32_t)buf * 4u * TILEEL * 2u; \
    int k0 = (s) << 5; \
    CP_ASYNC(sb + so0, Ah + (size_t)(row0 + lr0) * ldA + k0 + ls0*8); \
    CP_ASYNC(sb + so1, Ah + (size_t)(row0 + lr1) * ldA + k0 + ls1*8); \
    CP_ASYNC(sb + TILEEL*2 + so0, Al + (size_t)(row0 + lr0) * ldA + k0 + ls0*8); \
    CP_ASYNC(sb + TILEEL*2 + so1, Al + (size_t)(row0 + lr1) * ldA + k0 + ls1*8); \
    CP_ASYNC(sb + 2*TILEEL*2 + so0, Bh + (size_t)(n0 + lr0) * K + k0 + ls0*8); \
    CP_ASYNC(sb + 2*TILEEL*2 + so1, Bh + (size_t)(n0 + lr1) * K + k0 + ls1*8); \
    CP_ASYNC(sb + 3*TILEEL*2 + so0, Bl + (size_t)(n0 + lr0) * K + k0 + ls0*8); \
    CP_ASYNC(sb + 3*TILEEL*2 + so1, Bl + (size_t)(n0 + lr1) * K + k0 + ls1*8); \
} while (0)

    LOADSTAGE(0);
    CP_COMMIT();

    int arow = (lane & 15), acol = (lane >> 4) * 8;
    int brow = (lane & 7),  bcol = ((lane >> 3) & 1) * 8;

    for (int s = 0; s < S; s++) {
        if (s + 1 < S) { LOADSTAGE(s + 1); CP_COMMIT(); CP_WAIT(1); }
        else           { CP_WAIT(0); }
        __syncthreads();

        uint32_t sb = smbase + (uint32_t)(s & 1) * 4u * TILEEL * 2u;
        uint32_t Ah_s = sb, Al_s = sb + TILEEL*2, Bh_s = sb + 2*TILEEL*2, Bl_s = sb + 3*TILEEL*2;

#pragma unroll
        for (int ks = 0; ks < 2; ks++) {
            int k0 = ks * 16;
            uint32_t aH[4][4], aL[4][4];
#pragma unroll
            for (int mi = 0; mi < 4; mi++) {
                uint32_t off = (uint32_t)((wm*64 + mi*16 + arow) * ASTR + k0 + acol) * 2;
                ldsm_x4(aH[mi], Ah_s + off);
                ldsm_x4(aL[mi], Al_s + off);
            }
            uint32_t bH[4][2], bL[4][2];
#pragma unroll
            for (int ni = 0; ni < 4; ni++) {
                uint32_t off = (uint32_t)((wn*32 + ni*8 + brow) * ASTR + k0 + bcol) * 2;
                ldsm_x2(bH[ni], Bh_s + off);
                ldsm_x2(bL[ni], Bl_s + off);
            }
#pragma unroll
            for (int mi = 0; mi < 4; mi++)
#pragma unroll
                for (int ni = 0; ni < 4; ni++) {
                    mma16816(acc[mi][ni], aH[mi], bH[ni]);
                    mma16816(acc[mi][ni], aH[mi], bL[ni]);
                    mma16816(acc[mi][ni], aL[mi], bH[ni]);
                }
        }
        __syncthreads();
    }

    // epilogue (+ optional per-column stats)
    int g4 = lane >> 2, t4 = lane & 3;
    float cs[4][2], cq[4][2];
#pragma unroll
    for (int ni = 0; ni < 4; ni++) { cs[ni][0]=cs[ni][1]=cq[ni][0]=cq[ni][1]=0.f; }

#pragma unroll
    for (int mi = 0; mi < 4; mi++) {
        int r = row0 + wm*64 + mi*16 + g4;
#pragma unroll
        for (int ni = 0; ni < 4; ni++) {
            int c = n0 + wn*32 + ni*8 + t4*2;
            float b0 = 0.f, b1 = 0.f;
            if (bias) { b0 = bias[c]; b1 = bias[c+1]; }
            float v0 = acc[mi][ni][0] + b0, v1 = acc[mi][ni][1] + b1;
            float v2 = acc[mi][ni][2] + b0, v3 = acc[mi][ni][3] + b1;
            *(float2*)&out[(size_t)r * ldout + c]     = make_float2(v0, v1);
            *(float2*)&out[(size_t)(r+8) * ldout + c] = make_float2(v2, v3);
            cs[ni][0] += v0 + v2;  cq[ni][0] += v0*v0 + v2*v2;
            cs[ni][1] += v1 + v3;  cq[ni][1] += v1*v1 + v3*v3;
        }
    }
    if (stats) {
#pragma unroll
        for (int ni = 0; ni < 4; ni++) {
#pragma unroll
            for (int h = 0; h < 2; h++) {
                float s = cs[ni][h], q = cq[ni][h];
                s += __shfl_xor_sync(0xFFFFFFFFu, s, 4);
                q += __shfl_xor_sync(0xFFFFFFFFu, q, 4);
                s += __shfl_xor_sync(0xFFFFFFFFu, s, 8);
                q += __shfl_xor_sync(0xFFFFFFFFu, q, 8);
                s += __shfl_xor_sync(0xFFFFFFFFu, s, 16);
                q += __shfl_xor_sync(0xFFFFFFFFu, q, 16);
                if (g4 == 0) {
                    int c = n0 + wn*32 + ni*8 + t4*2 + h;
                    atomicAdd(&stats[c], s);
                    atomicAdd(&stats[256 + c], q);
                }
            }
        }
    }
}

// out = bn(h2) + x
__global__ void k_final(const float* __restrict__ x, const float* __restrict__ g,
                        const float* __restrict__ be, float* __restrict__ out) {
    int tid = threadIdx.x;
    __shared__ float sc[256], sh[256];
    {
        float mean = d_stats[1024 + tid] * (1.0f / NN);
        float var  = d_stats[1280 + tid] * (1.0f / NN) - mean * mean;
        float s = rsqrtf(var + BNEPS) * g[tid];
        sc[tid] = s;
        sh[tid] = be[tid] - mean * s;
    }
    __syncthreads();
    size_t i = (size_t)(blockIdx.x * 256 + tid) * 4;
    int c = (int)(i & 255);
    float4 h  = *(float4*)&d_h2[i];
    float4 xv = *(const float4*)&x[i];
    float4 o;
    o.x = h.x * sc[c+0] + sh[c+0] + xv.x;
    o.y = h.y * sc[c+1] + sh[c+1] + xv.y;
    o.z = h.z * sc[c+2] + sh[c+2] + xv.z;
    o.w = h.w * sc[c+3] + sh[c+3] + xv.w;
    *(float4*)&out[i] = o;
}

// ------------------------------- launch --------------------------------------
extern "C" void kernel_launch(void* const* d_in, const int* in_sizes, int n_in,
                              void* d_out, int out_size) {
    const float* x       = (const float*)d_in[0];
    const float* mass    = (const float*)d_in[1];
    const float* evals   = (const float*)d_in[2];
    const float* evecs   = (const float*)d_in[3];
    const int*   gx_rows = (const int*)  d_in[4];
    const int*   gx_cols = (const int*)  d_in[5];
    const float* gx_vals = (const float*)d_in[6];
    const int*   gy_rows = (const int*)  d_in[7];
    const int*   gy_cols = (const int*)  d_in[8];
    const float* gy_vals = (const float*)d_in[9];
    const float* dt      = (const float*)d_in[10];
    const float* A_re    = (const float*)d_in[11];
    const float* A_im    = (const float*)d_in[12];
    const float* W0      = (const float*)d_in[13];
    const float* b0      = (const float*)d_in[14];
    const float* g0      = (const float*)d_in[15];
    const float* be0     = (const float*)d_in[16];
    const float* W1      = (const float*)d_in[17];
    const float* b1      = (const float*)d_in[18];
    const float* g1      = (const float*)d_in[19];
    const float* be1     = (const float*)d_in[20];
    const float* W2      = (const float*)d_in[21];
    const float* b2      = (const float*)d_in[22];
    const float* g2      = (const float*)d_in[23];
    const float* be2     = (const float*)d_in[24];
    float* out = (float*)d_out;

    static int smem_set = 0;
    if (!smem_set) {
        cudaFuncSetAttribute(k_mma_gemm, cudaFuncAttributeMaxDynamicSharedMemorySize, GEMM_SMEM);
        cudaFuncSetAttribute(k_xspec_mma, cudaFuncAttributeMaxDynamicSharedMemorySize, GEMM_SMEM);
        smem_set = 1;
    }

    __nv_bfloat16 *Ah, *Al, *Bh, *Bl, *eH, *eL, *ytH, *ytL;
    float *bb, *h0, *h1, *h2, *stats, *xd;
    cudaGetSymbolAddress((void**)&Ah, d_Ah);
    cudaGetSymbolAddress((void**)&Al, d_Al);
    cudaGetSymbolAddress((void**)&Bh, d_Bh);
    cudaGetSymbolAddress((void**)&Bl, d_Bl);
    cudaGetSymbolAddress((void**)&eH, d_eH);
    cudaGetSymbolAddress((void**)&eL, d_eL);
    cudaGetSymbolAddress((void**)&ytH, d_ytH);
    cudaGetSymbolAddress((void**)&ytL, d_ytL);
    cudaGetSymbolAddress((void**)&bb, d_bb);
    cudaGetSymbolAddress((void**)&h0, d_h0);
    cudaGetSymbolAddress((void**)&h1, d_h1);
    cudaGetSymbolAddress((void**)&h2, d_h2);
    cudaGetSymbolAddress((void**)&stats, d_stats);
    cudaGetSymbolAddress((void**)&xd, d_xd);

    k_zero<<<16384, 256>>>();
    // spectral operand prep
    k_trans_mevecs<<<dim3(256, 4, 8), 256>>>(evecs, mass);
    k_trans_x<<<dim3(256, 8, 8), 256>>>(x);
    k_conv_evecs<<<8192, 256>>>(evecs);
    // x_spec (split-K tensor GEMM, atomic accumulate)
    k_xspec_mma<<<dim3(32, 2, 8), 256, GEMM_SMEM>>>();
    k_coefT<<<1024, 256>>>(evals, dt);
    // x_diffuse = evecs @ yT^T  (per-batch B)
    k_mma_gemm<<<dim3(512, 2), 256, GEMM_SMEM>>>(eH, eL, NK, ytH, ytL,
                                                 xd, 256, nullptr, NK, nullptr, NC*NK);
    // sparse gradients
    k_spmm<<<NNZ/4, 256>>>(gx_rows, gx_cols, gx_vals, 0);
    k_spmm<<<NNZ/4, 256>>>(gy_rows, gy_cols, gy_vals, 1);

    // weight prep (small)
    k_prep_cplxB<<<1024, 256>>>(A_re, A_im);
    k_prep_wT<<<768, 256>>>(W0, 768, 256, BOFF_W0);
    k_prep_wT<<<256, 256>>>(W1, 256, 256, BOFF_W1);
    k_prep_wT<<<256, 256>>>(W2, 256, 256, BOFF_W2);

    // complex gradient GEMM: [bre|bim] = [gX|gY] @ B'^T
    k_split_gxy<<<16384, 256>>>();
    k_mma_gemm<<<dim3(512, 4), 256, GEMM_SMEM>>>(Ah, Al, 768, Bh + BOFF_CPLX, Bl + BOFF_CPLX,
                                                 bb, 512, nullptr, 512, nullptr, 0);
    k_split2<<<16384, 256>>>(x);

    // MLP (stats fused into epilogues)
    k_mma_gemm<<<dim3(512, 2), 256, GEMM_SMEM>>>(Ah, Al, 768, Bh + BOFF_W0, Bl + BOFF_W0,
                                                 h0, 256, b0, 768, stats, 0);
    k_bnsplit<<<16384, 256>>>(h0, 0, g0, be0);
    k_mma_gemm<<<dim3(512, 2), 256, GEMM_SMEM>>>(Ah, Al, 768, Bh + BOFF_W1, Bl + BOFF_W1,
                                                 h1, 256, b1, 256, stats + 512, 0);
    k_bnsplit<<<16384, 256>>>(h1, 512, g1, be1);
    k_mma_gemm<<<dim3(512, 2), 256, GEMM_SMEM>>>(Ah, Al, 768, Bh + BOFF_W2, Bl + BOFF_W2,
                                                 h2, 256, b2, 256, stats + 1024, 0);
    k_final<<<16384, 256>>>(x, g2, be2, out);
}

// round 6
// speedup vs baseline: 2.0199x; 1.0820x over previous
#include <cuda_runtime.h>
#include <cuda_bf16.h>
#include <math.h>
#include <cstdint>

#define NB 8
#define NV 8192
#define NK 128
#define NC 256
#define NN 65536          // NB*NV
#define NNZ 1048576       // 16*NN
#define BNEPS 1e-5f

// ------------------------- scratch (device globals) -------------------------
static __device__ float d_xspec[NB*NK*NC];
static __device__ float d_xd  [NN*NC];
static __device__ float d_gX  [NN*NC];
static __device__ float d_gY  [NN*NC];
static __device__ float d_bb  [(size_t)NN*512];  // [bre | bim]
static __device__ float d_h0  [NN*NC];
static __device__ float d_h1  [NN*NC];
static __device__ float d_h2  [NN*NC];
static __device__ float d_stats[1536];
// bf16 split A: [NN, 768] hi/lo
static __device__ __nv_bfloat16 d_Ah[(size_t)NN*768];
static __device__ __nv_bfloat16 d_Al[(size_t)NN*768];
// bf16 split B pool: cplx(512x512) | W0T(256x768) | W1T(256x256) | W2T(256x256)
#define BOFF_CPLX 0
#define BOFF_W0   262144
#define BOFF_W1   458752
#define BOFF_W2   524288
static __device__ __nv_bfloat16 d_Bh[589824];
static __device__ __nv_bfloat16 d_Bl[589824];
// spectral operands (bf16 split)
static __device__ __nv_bfloat16 d_mtH[(size_t)NB*NK*NV];   // mevecs^T [b][k][v]
static __device__ __nv_bfloat16 d_mtL[(size_t)NB*NK*NV];
static __device__ __nv_bfloat16 d_xtH[(size_t)NB*NC*NV];   // x^T [b][c][v]
static __device__ __nv_bfloat16 d_xtL[(size_t)NB*NC*NV];
static __device__ __nv_bfloat16 d_eH[(size_t)NN*NK];       // evecs split (row-major)
static __device__ __nv_bfloat16 d_eL[(size_t)NN*NK];
static __device__ __nv_bfloat16 d_ytH[NB*NC*NK];           // (coef*xspec)^T [b][c][k]
static __device__ __nv_bfloat16 d_ytL[NB*NC*NK];

__device__ __forceinline__ uint32_t smem_u32(const void* p) {
    uint32_t a;
    asm("{ .reg .u64 t; cvta.to.shared.u64 t, %1; cvt.u32.u64 %0, t; }" : "=r"(a) : "l"(p));
    return a;
}

// packed bf16 split helpers
struct SplitPack { uint4 hi, lo; };
__device__ __forceinline__ SplitPack split8(float4 a, float4 b) {
    union { __nv_bfloat16 h[8]; uint4 u; } H;
    union { __nv_bfloat16 h[8]; uint4 u; } L;
    float v[8] = {a.x, a.y, a.z, a.w, b.x, b.y, b.z, b.w};
#pragma unroll
    for (int j = 0; j < 8; j++) {
        __nv_bfloat16 hh = __float2bfloat16(v[j]);
        H.h[j] = hh;
        L.h[j] = __float2bfloat16(v[j] - __bfloat162float(hh));
    }
    SplitPack r; r.hi = H.u; r.lo = L.u; return r;
}
struct SplitPack4 { uint2 hi, lo; };
__device__ __forceinline__ SplitPack4 split4(const float* v) {
    union { __nv_bfloat16 h[4]; uint2 u; } H;
    union { __nv_bfloat16 h[4]; uint2 u; } L;
#pragma unroll
    for (int j = 0; j < 4; j++) {
        __nv_bfloat16 hh = __float2bfloat16(v[j]);
        H.h[j] = hh;
        L.h[j] = __float2bfloat16(v[j] - __bfloat162float(hh));
    }
    SplitPack4 r; r.hi = H.u; r.lo = L.u; return r;
}

// ------------------------------- zero init ----------------------------------
__global__ void k_zero() {
    int i = (blockIdx.x * 256 + threadIdx.x) * 4;
    float4 z = make_float4(0.f, 0.f, 0.f, 0.f);
    *(float4*)&d_gX[i] = z;
    *(float4*)&d_gY[i] = z;
    if (i < NB*NK*NC) *(float4*)&d_xspec[i] = z;
    if (i < 1536)     *(float4*)&d_stats[i] = z;
}

// ===================== spectral operand preparation ==========================
// merged: mt (transposed, mass-weighted) + e (straight) from one evecs read.
// grid (256, 4, 8), 256 thr
__global__ __launch_bounds__(256) void k_trans_mevecs(
    const float* __restrict__ evecs, const float* __restrict__ mass) {
    __shared__ float tile[32][33];
    __shared__ float smass[32];
    int v0 = blockIdx.x * 32, k0 = blockIdx.y * 32, b = blockIdx.z;
    int tid = threadIdx.x;
    int tx = tid & 31, ty = tid >> 5;
    if (tid < 32) smass[tid] = mass[b * NV + v0 + tid];
#pragma unroll
    for (int i = 0; i < 4; i++) {
        int vl = ty + i * 8;
        tile[vl][tx] = evecs[(size_t)(b * NV + v0 + vl) * NK + k0 + tx];
    }
    __syncthreads();
    // transposed mass-weighted: k = tid>>3, vq = (tid&7)*4
    {
        int k = tid >> 3, vq = (tid & 7) * 4;
        float v[4];
#pragma unroll
        for (int j = 0; j < 4; j++) v[j] = tile[vq + j][k] * smass[vq + j];
        SplitPack4 p = split4(v);
        size_t o = (size_t)(b * NK + k0 + k) * NV + v0 + vq;
        *(uint2*)&d_mtH[o] = p.hi;
        *(uint2*)&d_mtL[o] = p.lo;
    }
    // straight: v = tid>>3, kq = (tid&7)*4
    {
        int v = tid >> 3, kq = (tid & 7) * 4;
        float w[4];
#pragma unroll
        for (int j = 0; j < 4; j++) w[j] = tile[v][kq + j];
        SplitPack4 p = split4(w);
        size_t o = (size_t)(b * NV + v0 + v) * NK + k0 + kq;
        *(uint2*)&d_eH[o] = p.hi;
        *(uint2*)&d_eL[o] = p.lo;
    }
}

// x^T: [b][c][v]. grid (256, 8, 8), 256 thr
__global__ __launch_bounds__(256) void k_trans_x(const float* __restrict__ x) {
    __shared__ float tile[32][33];
    int v0 = blockIdx.x * 32, c0 = blockIdx.y * 32, b = blockIdx.z;
    int tid = threadIdx.x;
    int tx = tid & 31, ty = tid >> 5;
#pragma unroll
    for (int i = 0; i < 4; i++) {
        int vl = ty + i * 8;
        tile[vl][tx] = x[(size_t)(b * NV + v0 + vl) * NC + c0 + tx];
    }
    __syncthreads();
    int c = tid >> 3, vq = (tid & 7) * 4;
    float v[4];
#pragma unroll
    for (int j = 0; j < 4; j++) v[j] = tile[vq + j][c];
    SplitPack4 p = split4(v);
    size_t o = (size_t)(b * NC + c0 + c) * NV + v0 + vq;
    *(uint2*)&d_xtH[o] = p.hi;
    *(uint2*)&d_xtL[o] = p.lo;
}

// yT[b][c][k], vectorized over k. grid 256, 256 thr
__global__ void k_coefT(const float* __restrict__ evals, const float* __restrict__ dt) {
    int i = blockIdx.x * 256 + threadIdx.x;   // < 65536
    int kq = (i & 31) * 4;
    int c  = (i >> 5) & 255;
    int b  = i >> 13;
    float t = fmaxf(dt[c], 1e-8f);
    float v[4];
#pragma unroll
    for (int j = 0; j < 4; j++)
        v[j] = expf(-evals[b * NK + kq + j] * t) * d_xspec[(b * NK + kq + j) * NC + c];
    SplitPack4 p = split4(v);
    int o = b * (NC * NK) + c * NK + kq;
    *(uint2*)&d_ytH[o] = p.hi;
    *(uint2*)&d_ytL[o] = p.lo;
}

// ============================ mma primitives =================================
__device__ __forceinline__ void ldsm_x4(uint32_t* r, uint32_t addr) {
    asm volatile("ldmatrix.sync.aligned.m8n8.x4.shared.b16 {%0,%1,%2,%3}, [%4];"
                 : "=r"(r[0]), "=r"(r[1]), "=r"(r[2]), "=r"(r[3]) : "r"(addr));
}
__device__ __forceinline__ void ldsm_x2(uint32_t* r, uint32_t addr) {
    asm volatile("ldmatrix.sync.aligned.m8n8.x2.shared.b16 {%0,%1}, [%2];"
                 : "=r"(r[0]), "=r"(r[1]) : "r"(addr));
}
__device__ __forceinline__ void mma16816(float* c, const uint32_t* a, const uint32_t* b) {
    asm volatile("mma.sync.aligned.m16n8k16.row.col.f32.bf16.bf16.f32 "
                 "{%0,%1,%2,%3}, {%4,%5,%6,%7}, {%8,%9}, {%0,%1,%2,%3};"
                 : "+f"(c[0]), "+f"(c[1]), "+f"(c[2]), "+f"(c[3])
                 : "r"(a[0]), "r"(a[1]), "r"(a[2]), "r"(a[3]), "r"(b[0]), "r"(b[1]));
}
#define CP_ASYNC(sm, gm) \
    asm volatile("cp.async.cg.shared.global [%0], [%1], 16;" :: "r"(sm), "l"(gm))
#define CP_COMMIT() asm volatile("cp.async.commit_group;" ::: "memory")
#define CP_WAIT(n)  asm volatile("cp.async.wait_group %0;" :: "n"(n) : "memory")

#define ASTR 40
#define TILEEL (128*ASTR)
#define GEMM_SMEM (2*4*TILEEL*2)   // 81920

// ------------------- x_spec split-K mma: grid (32, 2, 8) ---------------------
__global__ __launch_bounds__(256) void k_xspec_mma() {
    extern __shared__ __align__(16) __nv_bfloat16 sm[];
    int tid = threadIdx.x;
    int wid = tid >> 5, lane = tid & 31;
    int wm = wid & 1, wn = wid >> 1;
    int kb = blockIdx.x, ch = blockIdx.y, b = blockIdx.z;
    const __nv_bfloat16* Ah = d_mtH + (size_t)b * NK * NV;
    const __nv_bfloat16* Al = d_mtL + (size_t)b * NK * NV;
    const __nv_bfloat16* Bh = d_xtH + (size_t)(b * NC + ch * 128) * NV;
    const __nv_bfloat16* Bl = d_xtL + (size_t)(b * NC + ch * 128) * NV;
    int kbase = kb * 256;

    float acc[4][4][4];
#pragma unroll
    for (int mi = 0; mi < 4; mi++)
#pragma unroll
        for (int ni = 0; ni < 4; ni++)
#pragma unroll
            for (int q = 0; q < 4; q++) acc[mi][ni][q] = 0.f;

    int idx0 = tid * 2, idx1 = tid * 2 + 1;
    int lr0 = idx0 >> 2, ls0 = idx0 & 3;
    int lr1 = idx1 >> 2, ls1 = idx1 & 3;
    uint32_t so0 = (uint32_t)(lr0 * ASTR + ls0 * 8) * 2;
    uint32_t so1 = (uint32_t)(lr1 * ASTR + ls1 * 8) * 2;
    uint32_t smbase = smem_u32(sm);

#define XLOAD(s) do { \
    uint32_t sb = smbase + (uint32_t)((s) & 1) * 4u * TILEEL * 2u; \
    int k0 = kbase + ((s) << 5); \
    CP_ASYNC(sb + so0, Ah + (size_t)lr0 * NV + k0 + ls0*8); \
    CP_ASYNC(sb + so1, Ah + (size_t)lr1 * NV + k0 + ls1*8); \
    CP_ASYNC(sb + TILEEL*2 + so0, Al + (size_t)lr0 * NV + k0 + ls0*8); \
    CP_ASYNC(sb + TILEEL*2 + so1, Al + (size_t)lr1 * NV + k0 + ls1*8); \
    CP_ASYNC(sb + 2*TILEEL*2 + so0, Bh + (size_t)lr0 * NV + k0 + ls0*8); \
    CP_ASYNC(sb + 2*TILEEL*2 + so1, Bh + (size_t)lr1 * NV + k0 + ls1*8); \
    CP_ASYNC(sb + 3*TILEEL*2 + so0, Bl + (size_t)lr0 * NV + k0 + ls0*8); \
    CP_ASYNC(sb + 3*TILEEL*2 + so1, Bl + (size_t)lr1 * NV + k0 + ls1*8); \
} while (0)

    XLOAD(0);
    CP_COMMIT();

    int arow = (lane & 15), acol = (lane >> 4) * 8;
    int brow = (lane & 7),  bcol = ((lane >> 3) & 1) * 8;

    for (int s = 0; s < 8; s++) {
        if (s + 1 < 8) { XLOAD(s + 1); CP_COMMIT(); CP_WAIT(1); }
        else           { CP_WAIT(0); }
        __syncthreads();
        uint32_t sb = smbase + (uint32_t)(s & 1) * 4u * TILEEL * 2u;
        uint32_t Ah_s = sb, Al_s = sb + TILEEL*2, Bh_s = sb + 2*TILEEL*2, Bl_s = sb + 3*TILEEL*2;
#pragma unroll
        for (int ks = 0; ks < 2; ks++) {
            int k0 = ks * 16;
            uint32_t aH[4][4], aL[4][4];
#pragma unroll
            for (int mi = 0; mi < 4; mi++) {
                uint32_t off = (uint32_t)((wm*64 + mi*16 + arow) * ASTR + k0 + acol) * 2;
                ldsm_x4(aH[mi], Ah_s + off);
                ldsm_x4(aL[mi], Al_s + off);
            }
            uint32_t bH[4][2], bL[4][2];
#pragma unroll
            for (int ni = 0; ni < 4; ni++) {
                uint32_t off = (uint32_t)((wn*32 + ni*8 + brow) * ASTR + k0 + bcol) * 2;
                ldsm_x2(bH[ni], Bh_s + off);
                ldsm_x2(bL[ni], Bl_s + off);
            }
#pragma unroll
            for (int mi = 0; mi < 4; mi++)
#pragma unroll
                for (int ni = 0; ni < 4; ni++) {
                    mma16816(acc[mi][ni], aH[mi], bH[ni]);
                    mma16816(acc[mi][ni], aH[mi], bL[ni]);
                    mma16816(acc[mi][ni], aL[mi], bH[ni]);
                }
        }
        __syncthreads();
    }

    int g4 = lane >> 2, t4 = lane & 3;
#pragma unroll
    for (int mi = 0; mi < 4; mi++) {
        int r = wm*64 + mi*16 + g4;
#pragma unroll
        for (int ni = 0; ni < 4; ni++) {
            int c = ch*128 + wn*32 + ni*8 + t4*2;
            float* o0 = &d_xspec[(b*NK + r) * NC + c];
            float* o1 = &d_xspec[(b*NK + r + 8) * NC + c];
            asm volatile("red.global.add.v2.f32 [%0], {%1,%2};"
                         :: "l"(o0), "f"(acc[mi][ni][0]), "f"(acc[mi][ni][1]) : "memory");
            asm volatile("red.global.add.v2.f32 [%0], {%1,%2};"
                         :: "l"(o1), "f"(acc[mi][ni][2]), "f"(acc[mi][ni][3]) : "memory");
        }
    }
}

// SpMM scatter with 16B vector reductions
__global__ void k_spmm(const int* __restrict__ rows, const int* __restrict__ cols,
                       const float* __restrict__ vals, int which) {
    int tid = threadIdx.x;
    int e = blockIdx.x * 4 + (tid >> 6);
    int c = (tid & 63) * 4;
    int r  = rows[e];
    int cl = cols[e];
    float v = vals[e];
    float* out = which ? d_gY : d_gX;
    float4 s = *(const float4*)&d_xd[(size_t)cl * NC + c];
    float* o = out + (size_t)r * NC + c;
    asm volatile("red.global.add.v4.f32 [%0], {%1,%2,%3,%4};"
                 :: "l"(o), "f"(v*s.x), "f"(v*s.y), "f"(v*s.z), "f"(v*s.w) : "memory");
}

// ========================== B-operand prep (bf16 split) ======================
__global__ void k_prep_cplxB(const float* __restrict__ Are, const float* __restrict__ Aim) {
    int i = blockIdx.x * 256 + threadIdx.x;   // < 262144
    int n = i >> 9, k = i & 511;
    float v;
    if (n < 256) v = (k < 256) ? Are[n*256 + k] : -Aim[n*256 + (k-256)];
    else {
        int n2 = n - 256;
        v = (k < 256) ? Aim[n2*256 + k] : Are[n2*256 + (k-256)];
    }
    __nv_bfloat16 h = __float2bfloat16(v);
    d_Bh[BOFF_CPLX + i] = h;
    d_Bl[BOFF_CPLX + i] = __float2bfloat16(v - __bfloat162float(h));
}

__global__ void k_prep_wT(const float* __restrict__ W, int K, int N, int off) {
    int i = blockIdx.x * 256 + threadIdx.x;
    if (i >= N * K) return;
    int n = i / K, k = i % K;
    float v = W[k*N + n];
    __nv_bfloat16 h = __float2bfloat16(v);
    d_Bh[off + i] = h;
    d_Bl[off + i] = __float2bfloat16(v - __bfloat162float(h));
}

// ========================= activation splits (vectorized) ====================
// A cols [0..511] = [gX | gY]. grid 8192, 256 thr; thread = 8 channels
__global__ void k_split_gxy() {
    int idx = blockIdx.x * 256 + threadIdx.x;  // < 2097152
    size_t row = idx >> 5;
    int c = (idx & 31) * 8;
    const float* gx = &d_gX[row * 256 + c];
    const float* gy = &d_gY[row * 256 + c];
    SplitPack px = split8(*(const float4*)gx, *(const float4*)(gx + 4));
    SplitPack py = split8(*(const float4*)gy, *(const float4*)(gy + 4));
    size_t base = row * 768;
    *(uint4*)&d_Ah[base + c]       = px.hi;
    *(uint4*)&d_Al[base + c]       = px.lo;
    *(uint4*)&d_Ah[base + 256 + c] = py.hi;
    *(uint4*)&d_Al[base + 256 + c] = py.lo;
}

// post-cplx merged: cols [0..255]=x, [256..511]=xd, [512..767]=tanh(gX*bre+gY*bim)
__global__ void k_split2(const float* __restrict__ x) {
    int idx = blockIdx.x * 256 + threadIdx.x;  // < 2097152
    size_t row = idx >> 5;
    int c = (idx & 31) * 8;
    size_t o = row * 256 + c;
    float4 xv0 = *(const float4*)&x[o],      xv1 = *(const float4*)&x[o + 4];
    float4 xd0 = *(const float4*)&d_xd[o],   xd1 = *(const float4*)&d_xd[o + 4];
    float4 gx0 = *(const float4*)&d_gX[o],   gx1 = *(const float4*)&d_gX[o + 4];
    float4 gy0 = *(const float4*)&d_gY[o],   gy1 = *(const float4*)&d_gY[o + 4];
    size_t bo = row * 512 + c;
    float4 br0 = *(const float4*)&d_bb[bo],       br1 = *(const float4*)&d_bb[bo + 4];
    float4 bi0 = *(const float4*)&d_bb[bo + 256], bi1 = *(const float4*)&d_bb[bo + 260];
    float4 t0, t1;
    t0.x = tanhf(gx0.x*br0.x + gy0.x*bi0.x);
    t0.y = tanhf(gx0.y*br0.y + gy0.y*bi0.y);
    t0.z = tanhf(gx0.z*br0.z + gy0.z*bi0.z);
    t0.w = tanhf(gx0.w*br0.w + gy0.w*bi0.w);
    t1.x = tanhf(gx1.x*br1.x + gy1.x*bi1.x);
    t1.y = tanhf(gx1.y*br1.y + gy1.y*bi1.y);
    t1.z = tanhf(gx1.z*br1.z + gy1.z*bi1.z);
    t1.w = tanhf(gx1.w*br1.w + gy1.w*bi1.w);
    SplitPack p0 = split8(xv0, xv1);
    SplitPack p1 = split8(xd0, xd1);
    SplitPack p2 = split8(t0, t1);
    size_t base = row * 768;
    *(uint4*)&d_Ah[base + c]       = p0.hi;  *(uint4*)&d_Al[base + c]       = p0.lo;
    *(uint4*)&d_Ah[base + 256 + c] = p1.hi;  *(uint4*)&d_Al[base + 256 + c] = p1.lo;
    *(uint4*)&d_Ah[base + 512 + c] = p2.hi;  *(uint4*)&d_Al[base + 512 + c] = p2.lo;
}

// relu(bn(h)) -> A cols [0..255]. grid 8192, 256 thr
__global__ void k_bnsplit(const float* __restrict__ h, int statoff,
                          const float* __restrict__ g, const float* __restrict__ be) {
    int tid = threadIdx.x;
    __shared__ float sc[256], sh[256];
    {
        float mean = d_stats[statoff + tid] * (1.0f / NN);
        float var  = d_stats[statoff + 256 + tid] * (1.0f / NN) - mean * mean;
        float s = rsqrtf(var + BNEPS) * g[tid];
        sc[tid] = s;
        sh[tid] = be[tid] - mean * s;
    }
    __syncthreads();
    int idx = blockIdx.x * 256 + tid;          // < 2097152
    size_t row = idx >> 5;
    int c = (idx & 31) * 8;
    size_t o = row * 256 + c;
    float4 h0 = *(const float4*)&h[o], h1 = *(const float4*)&h[o + 4];
    float4 v0, v1;
    v0.x = fmaxf(h0.x * sc[c+0] + sh[c+0], 0.f);
    v0.y = fmaxf(h0.y * sc[c+1] + sh[c+1], 0.f);
    v0.z = fmaxf(h0.z * sc[c+2] + sh[c+2], 0.f);
    v0.w = fmaxf(h0.w * sc[c+3] + sh[c+3], 0.f);
    v1.x = fmaxf(h1.x * sc[c+4] + sh[c+4], 0.f);
    v1.y = fmaxf(h1.y * sc[c+5] + sh[c+5], 0.f);
    v1.z = fmaxf(h1.z * sc[c+6] + sh[c+6], 0.f);
    v1.w = fmaxf(h1.w * sc[c+7] + sh[c+7], 0.f);
    SplitPack p = split8(v0, v1);
    size_t base = row * 768;
    *(uint4*)&d_Ah[base + c] = p.hi;
    *(uint4*)&d_Al[base + c] = p.lo;
}

// ========================= generic mma.sync bf16-split GEMM ==================
__global__ __launch_bounds__(256) void k_mma_gemm(
    const __nv_bfloat16* __restrict__ Ah, const __nv_bfloat16* __restrict__ Al, int ldA,
    const __nv_bfloat16* __restrict__ Bh, const __nv_bfloat16* __restrict__ Bl,
    float* __restrict__ out, int ldout, const float* __restrict__ bias, int K,
    float* __restrict__ stats, int bstrideB)
{
    extern __shared__ __align__(16) __nv_bfloat16 sm[];
    int tid = threadIdx.x;
    int wid = tid >> 5, lane = tid & 31;
    int wm = wid & 1, wn = wid >> 1;
    int row0 = blockIdx.x * 128, n0 = blockIdx.y * 128;
    if (bstrideB) {
        int b = row0 / NV;
        Bh += (size_t)b * bstrideB;
        Bl += (size_t)b * bstrideB;
    }

    float acc[4][4][4];
#pragma unroll
    for (int mi = 0; mi < 4; mi++)
#pragma unroll
        for (int ni = 0; ni < 4; ni++)
#pragma unroll
            for (int q = 0; q < 4; q++) acc[mi][ni][q] = 0.f;

    int idx0 = tid * 2, idx1 = tid * 2 + 1;
    int lr0 = idx0 >> 2, ls0 = idx0 & 3;
    int lr1 = idx1 >> 2, ls1 = idx1 & 3;
    uint32_t so0 = (uint32_t)(lr0 * ASTR + ls0 * 8) * 2;
    uint32_t so1 = (uint32_t)(lr1 * ASTR + ls1 * 8) * 2;
    uint32_t smbase = smem_u32(sm);

    const int S = K >> 5;

#define LOADSTAGE(s) do { \
    int buf = (s) & 1; \
    uint32_t sb = smbase + (uint32_t)buf * 4u * TILEEL * 2u; \
    int k0 = (s) << 5; \
    CP_ASYNC(sb + so0, Ah + (size_t)(row0 + lr0) * ldA + k0 + ls0*8); \
    CP_ASYNC(sb + so1, Ah + (size_t)(row0 + lr1) * ldA + k0 + ls1*8); \
    CP_ASYNC(sb + TILEEL*2 + so0, Al + (size_t)(row0 + lr0) * ldA + k0 + ls0*8); \
    CP_ASYNC(sb + TILEEL*2 + so1, Al + (size_t)(row0 + lr1) * ldA + k0 + ls1*8); \
    CP_ASYNC(sb + 2*TILEEL*2 + so0, Bh + (size_t)(n0 + lr0) * K + k0 + ls0*8); \
    CP_ASYNC(sb + 2*TILEEL*2 + so1, Bh + (size_t)(n0 + lr1) * K + k0 + ls1*8); \
    CP_ASYNC(sb + 3*TILEEL*2 + so0, Bl + (size_t)(n0 + lr0) * K + k0 + ls0*8); \
    CP_ASYNC(sb + 3*TILEEL*2 + so1, Bl + (size_t)(n0 + lr1) * K + k0 + ls1*8); \
} while (0)

    LOADSTAGE(0);
    CP_COMMIT();

    int arow = (lane & 15), acol = (lane >> 4) * 8;
    int brow = (lane & 7),  bcol = ((lane >> 3) & 1) * 8;

    for (int s = 0; s < S; s++) {
        if (s + 1 < S) { LOADSTAGE(s + 1); CP_COMMIT(); CP_WAIT(1); }
        else           { CP_WAIT(0); }
        __syncthreads();

        uint32_t sb = smbase + (uint32_t)(s & 1) * 4u * TILEEL * 2u;
        uint32_t Ah_s = sb, Al_s = sb + TILEEL*2, Bh_s = sb + 2*TILEEL*2, Bl_s = sb + 3*TILEEL*2;

#pragma unroll
        for (int ks = 0; ks < 2; ks++) {
            int k0 = ks * 16;
            uint32_t aH[4][4], aL[4][4];
#pragma unroll
            for (int mi = 0; mi < 4; mi++) {
                uint32_t off = (uint32_t)((wm*64 + mi*16 + arow) * ASTR + k0 + acol) * 2;
                ldsm_x4(aH[mi], Ah_s + off);
                ldsm_x4(aL[mi], Al_s + off);
            }
            uint32_t bH[4][2], bL[4][2];
#pragma unroll
            for (int ni = 0; ni < 4; ni++) {
                uint32_t off = (uint32_t)((wn*32 + ni*8 + brow) * ASTR + k0 + bcol) * 2;
                ldsm_x2(bH[ni], Bh_s + off);
                ldsm_x2(bL[ni], Bl_s + off);
            }
#pragma unroll
            for (int mi = 0; mi < 4; mi++)
#pragma unroll
                for (int ni = 0; ni < 4; ni++) {
                    mma16816(acc[mi][ni], aH[mi], bH[ni]);
                    mma16816(acc[mi][ni], aH[mi], bL[ni]);
                    mma16816(acc[mi][ni], aL[mi], bH[ni]);
                }
        }
        __syncthreads();
    }

    // epilogue (+ optional per-column stats)
    int g4 = lane >> 2, t4 = lane & 3;
    float cs[4][2], cq[4][2];
#pragma unroll
    for (int ni = 0; ni < 4; ni++) { cs[ni][0]=cs[ni][1]=cq[ni][0]=cq[ni][1]=0.f; }

#pragma unroll
    for (int mi = 0; mi < 4; mi++) {
        int r = row0 + wm*64 + mi*16 + g4;
#pragma unroll
        for (int ni = 0; ni < 4; ni++) {
            int c = n0 + wn*32 + ni*8 + t4*2;
            float b0 = 0.f, b1 = 0.f;
            if (bias) { b0 = bias[c]; b1 = bias[c+1]; }
            float v0 = acc[mi][ni][0] + b0, v1 = acc[mi][ni][1] + b1;
            float v2 = acc[mi][ni][2] + b0, v3 = acc[mi][ni][3] + b1;
            *(float2*)&out[(size_t)r * ldout + c]     = make_float2(v0, v1);
            *(float2*)&out[(size_t)(r+8) * ldout + c] = make_float2(v2, v3);
            cs[ni][0] += v0 + v2;  cq[ni][0] += v0*v0 + v2*v2;
            cs[ni][1] += v1 + v3;  cq[ni][1] += v1*v1 + v3*v3;
        }
    }
    if (stats) {
#pragma unroll
        for (int ni = 0; ni < 4; ni++) {
#pragma unroll
            for (int h = 0; h < 2; h++) {
                float s = cs[ni][h], q = cq[ni][h];
                s += __shfl_xor_sync(0xFFFFFFFFu, s, 4);
                q += __shfl_xor_sync(0xFFFFFFFFu, q, 4);
                s += __shfl_xor_sync(0xFFFFFFFFu, s, 8);
                q += __shfl_xor_sync(0xFFFFFFFFu, q, 8);
                s += __shfl_xor_sync(0xFFFFFFFFu, s, 16);
                q += __shfl_xor_sync(0xFFFFFFFFu, q, 16);
                if (g4 == 0) {
                    int c = n0 + wn*32 + ni*8 + t4*2 + h;
                    atomicAdd(&stats[c], s);
                    atomicAdd(&stats[256 + c], q);
                }
            }
        }
    }
}

// out = bn(h2) + x
__global__ void k_final(const float* __restrict__ x, const float* __restrict__ g,
                        const float* __restrict__ be, float* __restrict__ out) {
    int tid = threadIdx.x;
    __shared__ float sc[256], sh[256];
    {
        float mean = d_stats[1024 + tid] * (1.0f / NN);
        float var  = d_stats[1280 + tid] * (1.0f / NN) - mean * mean;
        float s = rsqrtf(var + BNEPS) * g[tid];
        sc[tid] = s;
        sh[tid] = be[tid] - mean * s;
    }
    __syncthreads();
    size_t i = (size_t)(blockIdx.x * 256 + tid) * 4;
    int c = (int)(i & 255);
    float4 h  = *(float4*)&d_h2[i];
    float4 xv = *(const float4*)&x[i];
    float4 o;
    o.x = h.x * sc[c+0] + sh[c+0] + xv.x;
    o.y = h.y * sc[c+1] + sh[c+1] + xv.y;
    o.z = h.z * sc[c+2] + sh[c+2] + xv.z;
    o.w = h.w * sc[c+3] + sh[c+3] + xv.w;
    *(float4*)&out[i] = o;
}

// ------------------------------- launch --------------------------------------
extern "C" void kernel_launch(void* const* d_in, const int* in_sizes, int n_in,
                              void* d_out, int out_size) {
    const float* x       = (const float*)d_in[0];
    const float* mass    = (const float*)d_in[1];
    const float* evals   = (const float*)d_in[2];
    const float* evecs   = (const float*)d_in[3];
    const int*   gx_rows = (const int*)  d_in[4];
    const int*   gx_cols = (const int*)  d_in[5];
    const float* gx_vals = (const float*)d_in[6];
    const int*   gy_rows = (const int*)  d_in[7];
    const int*   gy_cols = (const int*)  d_in[8];
    const float* gy_vals = (const float*)d_in[9];
    const float* dt      = (const float*)d_in[10];
    const float* A_re    = (const float*)d_in[11];
    const float* A_im    = (const float*)d_in[12];
    const float* W0      = (const float*)d_in[13];
    const float* b0      = (const float*)d_in[14];
    const float* g0      = (const float*)d_in[15];
    const float* be0     = (const float*)d_in[16];
    const float* W1      = (const float*)d_in[17];
    const float* b1      = (const float*)d_in[18];
    const float* g1      = (const float*)d_in[19];
    const float* be1     = (const float*)d_in[20];
    const float* W2      = (const float*)d_in[21];
    const float* b2      = (const float*)d_in[22];
    const float* g2      = (const float*)d_in[23];
    const float* be2     = (const float*)d_in[24];
    float* out = (float*)d_out;

    static int smem_set = 0;
    if (!smem_set) {
        cudaFuncSetAttribute(k_mma_gemm, cudaFuncAttributeMaxDynamicSharedMemorySize, GEMM_SMEM);
        cudaFuncSetAttribute(k_xspec_mma, cudaFuncAttributeMaxDynamicSharedMemorySize, GEMM_SMEM);
        smem_set = 1;
    }

    __nv_bfloat16 *Ah, *Al, *Bh, *Bl, *eH, *eL, *ytH, *ytL;
    float *bb, *h0, *h1, *h2, *stats, *xd;
    cudaGetSymbolAddress((void**)&Ah, d_Ah);
    cudaGetSymbolAddress((void**)&Al, d_Al);
    cudaGetSymbolAddress((void**)&Bh, d_Bh);
    cudaGetSymbolAddress((void**)&Bl, d_Bl);
    cudaGetSymbolAddress((void**)&eH, d_eH);
    cudaGetSymbolAddress((void**)&eL, d_eL);
    cudaGetSymbolAddress((void**)&ytH, d_ytH);
    cudaGetSymbolAddress((void**)&ytL, d_ytL);
    cudaGetSymbolAddress((void**)&bb, d_bb);
    cudaGetSymbolAddress((void**)&h0, d_h0);
    cudaGetSymbolAddress((void**)&h1, d_h1);
    cudaGetSymbolAddress((void**)&h2, d_h2);
    cudaGetSymbolAddress((void**)&stats, d_stats);
    cudaGetSymbolAddress((void**)&xd, d_xd);

    k_zero<<<16384, 256>>>();
    // spectral operand prep (merged evecs read: mt + e)
    k_trans_mevecs<<<dim3(256, 4, 8), 256>>>(evecs, mass);
    k_trans_x<<<dim3(256, 8, 8), 256>>>(x);
    // x_spec (split-K tensor GEMM, atomic accumulate)
    k_xspec_mma<<<dim3(32, 2, 8), 256, GEMM_SMEM>>>();
    k_coefT<<<256, 256>>>(evals, dt);
    // x_diffuse = evecs @ yT^T  (per-batch B)
    k_mma_gemm<<<dim3(512, 2), 256, GEMM_SMEM>>>(eH, eL, NK, ytH, ytL,
                                                 xd, 256, nullptr, NK, nullptr, NC*NK);
    // sparse gradients
    k_spmm<<<NNZ/4, 256>>>(gx_rows, gx_cols, gx_vals, 0);
    k_spmm<<<NNZ/4, 256>>>(gy_rows, gy_cols, gy_vals, 1);

    // weight prep (small)
    k_prep_cplxB<<<1024, 256>>>(A_re, A_im);
    k_prep_wT<<<768, 256>>>(W0, 768, 256, BOFF_W0);
    k_prep_wT<<<256, 256>>>(W1, 256, 256, BOFF_W1);
    k_prep_wT<<<256, 256>>>(W2, 256, 256, BOFF_W2);

    // complex gradient GEMM: [bre|bim] = [gX|gY] @ B'^T
    k_split_gxy<<<8192, 256>>>();
    k_mma_gemm<<<dim3(512, 4), 256, GEMM_SMEM>>>(Ah, Al, 768, Bh + BOFF_CPLX, Bl + BOFF_CPLX,
                                                 bb, 512, nullptr, 512, nullptr, 0);
    k_split2<<<8192, 256>>>(x);

    // MLP (stats fused into epilogues)
    k_mma_gemm<<<dim3(512, 2), 256, GEMM_SMEM>>>(Ah, Al, 768, Bh + BOFF_W0, Bl + BOFF_W0,
                                                 h0, 256, b0, 768, stats, 0);
    k_bnsplit<<<8192, 256>>>(h0, 0, g0, be0);
    k_mma_gemm<<<dim3(512, 2), 256, GEMM_SMEM>>>(Ah, Al, 768, Bh + BOFF_W1, Bl + BOFF_W1,
                                                 h1, 256, b1, 256, stats + 512, 0);
    k_bnsplit<<<8192, 256>>>(h1, 512, g1, be1);
    k_mma_gemm<<<dim3(512, 2), 256, GEMM_SMEM>>>(Ah, Al, 768, Bh + BOFF_W2, Bl + BOFF_W2,
                                                 h2, 256, b2, 256, stats + 1024, 0);
    k_final<<<16384, 256>>>(x, g2, be2, out);
}

// round 7
// speedup vs baseline: 2.5901x; 1.2823x over previous
#include <cuda_runtime.h>
#include <cuda_bf16.h>
#include <math.h>
#include <cstdint>

#define NB 8
#define NV 8192
#define NK 128
#define NC 256
#define NN 65536          // NB*NV
#define NNZ 1048576       // 16*NN
#define BNEPS 1e-5f

// ------------------------- scratch (device globals) -------------------------
static __device__ float d_xspec[NB*NK*NC];
static __device__ float d_xd  [NN*NC];
static __device__ float d_gX  [NN*NC];
static __device__ float d_gY  [NN*NC];
static __device__ float d_bb  [(size_t)NN*512];  // [bre | bim]
static __device__ float d_h0  [NN*NC];
static __device__ float d_h1  [NN*NC];
static __device__ float d_h2  [NN*NC];
static __device__ float d_stats[1536];
// CSR build scratch
static __device__ int d_cnt [131072];            // becomes cpos (end after scatter)
static __device__ int d_off [131072];            // exclusive starts
static __device__ int d_bsum[512];
static __device__ int d_perm[2*NNZ];
// bf16 split A: [NN, 768] hi/lo
static __device__ __nv_bfloat16 d_Ah[(size_t)NN*768];
static __device__ __nv_bfloat16 d_Al[(size_t)NN*768];
// bf16 split B pool: cplx(512x512) | W0T(256x768) | W1T(256x256) | W2T(256x256)
#define BOFF_CPLX 0
#define BOFF_W0   262144
#define BOFF_W1   458752
#define BOFF_W2   524288
static __device__ __nv_bfloat16 d_Bh[589824];
static __device__ __nv_bfloat16 d_Bl[589824];
// spectral operands (bf16 split)
static __device__ __nv_bfloat16 d_mtH[(size_t)NB*NK*NV];   // mevecs^T [b][k][v]
static __device__ __nv_bfloat16 d_mtL[(size_t)NB*NK*NV];
static __device__ __nv_bfloat16 d_xtH[(size_t)NB*NC*NV];   // x^T [b][c][v]
static __device__ __nv_bfloat16 d_xtL[(size_t)NB*NC*NV];
static __device__ __nv_bfloat16 d_eH[(size_t)NN*NK];       // evecs split (row-major)
static __device__ __nv_bfloat16 d_eL[(size_t)NN*NK];
static __device__ __nv_bfloat16 d_ytH[NB*NC*NK];           // (coef*xspec)^T [b][c][k]
static __device__ __nv_bfloat16 d_ytL[NB*NC*NK];

__device__ __forceinline__ uint32_t smem_u32(const void* p) {
    uint32_t a;
    asm("{ .reg .u64 t; cvta.to.shared.u64 t, %1; cvt.u32.u64 %0, t; }" : "=r"(a) : "l"(p));
    return a;
}

// packed bf16 split helpers
struct SplitPack { uint4 hi, lo; };
__device__ __forceinline__ SplitPack split8(float4 a, float4 b) {
    union { __nv_bfloat16 h[8]; uint4 u; } H;
    union { __nv_bfloat16 h[8]; uint4 u; } L;
    float v[8] = {a.x, a.y, a.z, a.w, b.x, b.y, b.z, b.w};
#pragma unroll
    for (int j = 0; j < 8; j++) {
        __nv_bfloat16 hh = __float2bfloat16(v[j]);
        H.h[j] = hh;
        L.h[j] = __float2bfloat16(v[j] - __bfloat162float(hh));
    }
    SplitPack r; r.hi = H.u; r.lo = L.u; return r;
}
struct SplitPack4 { uint2 hi, lo; };
__device__ __forceinline__ SplitPack4 split4(const float* v) {
    union { __nv_bfloat16 h[4]; uint2 u; } H;
    union { __nv_bfloat16 h[4]; uint2 u; } L;
#pragma unroll
    for (int j = 0; j < 4; j++) {
        __nv_bfloat16 hh = __float2bfloat16(v[j]);
        H.h[j] = hh;
        L.h[j] = __float2bfloat16(v[j] - __bfloat162float(hh));
    }
    SplitPack4 r; r.hi = H.u; r.lo = L.u; return r;
}

// ------------------------------- zero init ----------------------------------
// grid 256 x 256 threads: xspec (262144 f), cnt (131072 i), stats (1536 f)
__global__ void k_zero() {
    int i = blockIdx.x * 256 + threadIdx.x;     // < 65536
    float4 z = make_float4(0.f, 0.f, 0.f, 0.f);
    *(float4*)&d_xspec[i * 4] = z;
    if (i < 32768) *(int4*)&d_cnt[i * 4] = make_int4(0, 0, 0, 0);
    if (i < 384)   *(float4*)&d_stats[i * 4] = z;
}

// ========================= CSR build (both matrices) =========================
__global__ void k_hist(const int* __restrict__ gxr, const int* __restrict__ gyr) {
    int i = blockIdx.x * 256 + threadIdx.x;     // < 1048576
    atomicAdd(&d_cnt[gxr[i]], 1);
    atomicAdd(&d_cnt[65536 + gyr[i]], 1);
}

// block-level exclusive scan (512 blocks x 256)
__global__ void k_scan1() {
    __shared__ int sh[256];
    int tid = threadIdx.x;
    int i = blockIdx.x * 256 + tid;
    int v = d_cnt[i];
    sh[tid] = v;
    __syncthreads();
    for (int o = 1; o < 256; o <<= 1) {
        int t = (tid >= o) ? sh[tid - o] : 0;
        __syncthreads();
        sh[tid] += t;
        __syncthreads();
    }
    d_off[i] = sh[tid] - v;
    if (tid == 255) d_bsum[blockIdx.x] = sh[255];
}

// scan of 512 block sums (1 block x 512) -> exclusive
__global__ void k_scan2() {
    __shared__ int sh[512];
    int tid = threadIdx.x;
    int v = d_bsum[tid];
    sh[tid] = v;
    __syncthreads();
    for (int o = 1; o < 512; o <<= 1) {
        int t = (tid >= o) ? sh[tid - o] : 0;
        __syncthreads();
        sh[tid] += t;
        __syncthreads();
    }
    d_bsum[tid] = sh[tid] - v;
}

// add block offsets; cnt becomes running cursor (starts at off)
__global__ void k_scan3() {
    int i = blockIdx.x * 256 + threadIdx.x;     // < 131072
    int v = d_off[i] + d_bsum[i >> 8];
    d_off[i] = v;
    d_cnt[i] = v;
}

__global__ void k_scatter(const int* __restrict__ gxr, const int* __restrict__ gyr) {
    int i = blockIdx.x * 256 + threadIdx.x;     // < 1048576
    int p = atomicAdd(&d_cnt[gxr[i]], 1);
    d_perm[p] = i;
    int q = atomicAdd(&d_cnt[65536 + gyr[i]], 1);
    d_perm[q] = i;
}

// CSR spmm: out[r,:] = sum_e vals[e]*xd[cols[e],:].  grid 16384, 256 thr
// group of 64 threads per row, 4 channels per thread.
__global__ __launch_bounds__(256) void k_spmm_csr(
    const int* __restrict__ cols, const float* __restrict__ vals,
    int base, float* __restrict__ out) {
    int g = threadIdx.x >> 6, t = threadIdx.x & 63;
    int r = blockIdx.x * 4 + g;
    int idx = base + r;
    int s = d_off[idx], e = d_cnt[idx];
    int c = t * 4;
    float4 acc = make_float4(0.f, 0.f, 0.f, 0.f);
    int p = s;
    for (; p + 4 <= e; p += 4) {
        int e0 = d_perm[p], e1 = d_perm[p+1], e2 = d_perm[p+2], e3 = d_perm[p+3];
        int c0 = cols[e0], c1 = cols[e1], c2 = cols[e2], c3 = cols[e3];
        float v0 = vals[e0], v1 = vals[e1], v2 = vals[e2], v3 = vals[e3];
        float4 x0 = *(const float4*)&d_xd[(size_t)c0 * NC + c];
        float4 x1 = *(const float4*)&d_xd[(size_t)c1 * NC + c];
        float4 x2 = *(const float4*)&d_xd[(size_t)c2 * NC + c];
        float4 x3 = *(const float4*)&d_xd[(size_t)c3 * NC + c];
        acc.x += v0*x0.x + v1*x1.x + v2*x2.x + v3*x3.x;
        acc.y += v0*x0.y + v1*x1.y + v2*x2.y + v3*x3.y;
        acc.z += v0*x0.z + v1*x1.z + v2*x2.z + v3*x3.z;
        acc.w += v0*x0.w + v1*x1.w + v2*x2.w + v3*x3.w;
    }
    for (; p < e; p++) {
        int ed = d_perm[p];
        int cl = cols[ed];
        float v = vals[ed];
        float4 xv = *(const float4*)&d_xd[(size_t)cl * NC + c];
        acc.x += v*xv.x; acc.y += v*xv.y; acc.z += v*xv.z; acc.w += v*xv.w;
    }
    *(float4*)&out[(size_t)r * NC + c] = acc;
}

// ===================== spectral operand preparation ==========================
__global__ __launch_bounds__(256) void k_trans_mevecs(
    const float* __restrict__ evecs, const float* __restrict__ mass) {
    __shared__ float tile[32][33];
    __shared__ float smass[32];
    int v0 = blockIdx.x * 32, k0 = blockIdx.y * 32, b = blockIdx.z;
    int tid = threadIdx.x;
    int tx = tid & 31, ty = tid >> 5;
    if (tid < 32) smass[tid] = mass[b * NV + v0 + tid];
#pragma unroll
    for (int i = 0; i < 4; i++) {
        int vl = ty + i * 8;
        tile[vl][tx] = evecs[(size_t)(b * NV + v0 + vl) * NK + k0 + tx];
    }
    __syncthreads();
    {
        int k = tid >> 3, vq = (tid & 7) * 4;
        float v[4];
#pragma unroll
        for (int j = 0; j < 4; j++) v[j] = tile[vq + j][k] * smass[vq + j];
        SplitPack4 p = split4(v);
        size_t o = (size_t)(b * NK + k0 + k) * NV + v0 + vq;
        *(uint2*)&d_mtH[o] = p.hi;
        *(uint2*)&d_mtL[o] = p.lo;
    }
    {
        int v = tid >> 3, kq = (tid & 7) * 4;
        float w[4];
#pragma unroll
        for (int j = 0; j < 4; j++) w[j] = tile[v][kq + j];
        SplitPack4 p = split4(w);
        size_t o = (size_t)(b * NV + v0 + v) * NK + k0 + kq;
        *(uint2*)&d_eH[o] = p.hi;
        *(uint2*)&d_eL[o] = p.lo;
    }
}

__global__ __launch_bounds__(256) void k_trans_x(const float* __restrict__ x) {
    __shared__ float tile[32][33];
    int v0 = blockIdx.x * 32, c0 = blockIdx.y * 32, b = blockIdx.z;
    int tid = threadIdx.x;
    int tx = tid & 31, ty = tid >> 5;
#pragma unroll
    for (int i = 0; i < 4; i++) {
        int vl = ty + i * 8;
        tile[vl][tx] = x[(size_t)(b * NV + v0 + vl) * NC + c0 + tx];
    }
    __syncthreads();
    int c = tid >> 3, vq = (tid & 7) * 4;
    float v[4];
#pragma unroll
    for (int j = 0; j < 4; j++) v[j] = tile[vq + j][c];
    SplitPack4 p = split4(v);
    size_t o = (size_t)(b * NC + c0 + c) * NV + v0 + vq;
    *(uint2*)&d_xtH[o] = p.hi;
    *(uint2*)&d_xtL[o] = p.lo;
}

__global__ void k_coefT(const float* __restrict__ evals, const float* __restrict__ dt) {
    int i = blockIdx.x * 256 + threadIdx.x;   // < 65536
    int kq = (i & 31) * 4;
    int c  = (i >> 5) & 255;
    int b  = i >> 13;
    float t = fmaxf(dt[c], 1e-8f);
    float v[4];
#pragma unroll
    for (int j = 0; j < 4; j++)
        v[j] = expf(-evals[b * NK + kq + j] * t) * d_xspec[(b * NK + kq + j) * NC + c];
    SplitPack4 p = split4(v);
    int o = b * (NC * NK) + c * NK + kq;
    *(uint2*)&d_ytH[o] = p.hi;
    *(uint2*)&d_ytL[o] = p.lo;
}

// ============================ mma primitives =================================
__device__ __forceinline__ void ldsm_x4(uint32_t* r, uint32_t addr) {
    asm volatile("ldmatrix.sync.aligned.m8n8.x4.shared.b16 {%0,%1,%2,%3}, [%4];"
                 : "=r"(r[0]), "=r"(r[1]), "=r"(r[2]), "=r"(r[3]) : "r"(addr));
}
__device__ __forceinline__ void ldsm_x2(uint32_t* r, uint32_t addr) {
    asm volatile("ldmatrix.sync.aligned.m8n8.x2.shared.b16 {%0,%1}, [%2];"
                 : "=r"(r[0]), "=r"(r[1]) : "r"(addr));
}
__device__ __forceinline__ void mma16816(float* c, const uint32_t* a, const uint32_t* b) {
    asm volatile("mma.sync.aligned.m16n8k16.row.col.f32.bf16.bf16.f32 "
                 "{%0,%1,%2,%3}, {%4,%5,%6,%7}, {%8,%9}, {%0,%1,%2,%3};"
                 : "+f"(c[0]), "+f"(c[1]), "+f"(c[2]), "+f"(c[3])
                 : "r"(a[0]), "r"(a[1]), "r"(a[2]), "r"(a[3]), "r"(b[0]), "r"(b[1]));
}
#define CP_ASYNC(sm, gm) \
    asm volatile("cp.async.cg.shared.global [%0], [%1], 16;" :: "r"(sm), "l"(gm))
#define CP_COMMIT() asm volatile("cp.async.commit_group;" ::: "memory")
#define CP_WAIT(n)  asm volatile("cp.async.wait_group %0;" :: "n"(n) : "memory")

#define ASTR 40
#define TILEEL (128*ASTR)
#define GEMM_SMEM (2*4*TILEEL*2)   // 81920

// ------------------- x_spec split-K mma: grid (32, 2, 8) ---------------------
__global__ __launch_bounds__(256) void k_xspec_mma() {
    extern __shared__ __align__(16) __nv_bfloat16 sm[];
    int tid = threadIdx.x;
    int wid = tid >> 5, lane = tid & 31;
    int wm = wid & 1, wn = wid >> 1;
    int kb = blockIdx.x, ch = blockIdx.y, b = blockIdx.z;
    const __nv_bfloat16* Ah = d_mtH + (size_t)b * NK * NV;
    const __nv_bfloat16* Al = d_mtL + (size_t)b * NK * NV;
    const __nv_bfloat16* Bh = d_xtH + (size_t)(b * NC + ch * 128) * NV;
    const __nv_bfloat16* Bl = d_xtL + (size_t)(b * NC + ch * 128) * NV;
    int kbase = kb * 256;

    float acc[4][4][4];
#pragma unroll
    for (int mi = 0; mi < 4; mi++)
#pragma unroll
        for (int ni = 0; ni < 4; ni++)
#pragma unroll
            for (int q = 0; q < 4; q++) acc[mi][ni][q] = 0.f;

    int idx0 = tid * 2, idx1 = tid * 2 + 1;
    int lr0 = idx0 >> 2, ls0 = idx0 & 3;
    int lr1 = idx1 >> 2, ls1 = idx1 & 3;
    uint32_t so0 = (uint32_t)(lr0 * ASTR + ls0 * 8) * 2;
    uint32_t so1 = (uint32_t)(lr1 * ASTR + ls1 * 8) * 2;
    uint32_t smbase = smem_u32(sm);

#define XLOAD(s) do { \
    uint32_t sb = smbase + (uint32_t)((s) & 1) * 4u * TILEEL * 2u; \
    int k0 = kbase + ((s) << 5); \
    CP_ASYNC(sb + so0, Ah + (size_t)lr0 * NV + k0 + ls0*8); \
    CP_ASYNC(sb + so1, Ah + (size_t)lr1 * NV + k0 + ls1*8); \
    CP_ASYNC(sb + TILEEL*2 + so0, Al + (size_t)lr0 * NV + k0 + ls0*8); \
    CP_ASYNC(sb + TILEEL*2 + so1, Al + (size_t)lr1 * NV + k0 + ls1*8); \
    CP_ASYNC(sb + 2*TILEEL*2 + so0, Bh + (size_t)lr0 * NV + k0 + ls0*8); \
    CP_ASYNC(sb + 2*TILEEL*2 + so1, Bh + (size_t)lr1 * NV + k0 + ls1*8); \
    CP_ASYNC(sb + 3*TILEEL*2 + so0, Bl + (size_t)lr0 * NV + k0 + ls0*8); \
    CP_ASYNC(sb + 3*TILEEL*2 + so1, Bl + (size_t)lr1 * NV + k0 + ls1*8); \
} while (0)

    XLOAD(0);
    CP_COMMIT();

    int arow = (lane & 15), acol = (lane >> 4) * 8;
    int brow = (lane & 7),  bcol = ((lane >> 3) & 1) * 8;

    for (int s = 0; s < 8; s++) {
        if (s + 1 < 8) { XLOAD(s + 1); CP_COMMIT(); CP_WAIT(1); }
        else           { CP_WAIT(0); }
        __syncthreads();
        uint32_t sb = smbase + (uint32_t)(s & 1) * 4u * TILEEL * 2u;
        uint32_t Ah_s = sb, Al_s = sb + TILEEL*2, Bh_s = sb + 2*TILEEL*2, Bl_s = sb + 3*TILEEL*2;
#pragma unroll
        for (int ks = 0; ks < 2; ks++) {
            int k0 = ks * 16;
            uint32_t aH[4][4], aL[4][4];
#pragma unroll
            for (int mi = 0; mi < 4; mi++) {
                uint32_t off = (uint32_t)((wm*64 + mi*16 + arow) * ASTR + k0 + acol) * 2;
                ldsm_x4(aH[mi], Ah_s + off);
                ldsm_x4(aL[mi], Al_s + off);
            }
            uint32_t bH[4][2], bL[4][2];
#pragma unroll
            for (int ni = 0; ni < 4; ni++) {
                uint32_t off = (uint32_t)((wn*32 + ni*8 + brow) * ASTR + k0 + bcol) * 2;
                ldsm_x2(bH[ni], Bh_s + off);
                ldsm_x2(bL[ni], Bl_s + off);
            }
#pragma unroll
            for (int mi = 0; mi < 4; mi++)
#pragma unroll
                for (int ni = 0; ni < 4; ni++) {
                    mma16816(acc[mi][ni], aH[mi], bH[ni]);
                    mma16816(acc[mi][ni], aH[mi], bL[ni]);
                    mma16816(acc[mi][ni], aL[mi], bH[ni]);
                }
        }
        __syncthreads();
    }

    int g4 = lane >> 2, t4 = lane & 3;
#pragma unroll
    for (int mi = 0; mi < 4; mi++) {
        int r = wm*64 + mi*16 + g4;
#pragma unroll
        for (int ni = 0; ni < 4; ni++) {
            int c = ch*128 + wn*32 + ni*8 + t4*2;
            float* o0 = &d_xspec[(b*NK + r) * NC + c];
            float* o1 = &d_xspec[(b*NK + r + 8) * NC + c];
            asm volatile("red.global.add.v2.f32 [%0], {%1,%2};"
                         :: "l"(o0), "f"(acc[mi][ni][0]), "f"(acc[mi][ni][1]) : "memory");
            asm volatile("red.global.add.v2.f32 [%0], {%1,%2};"
                         :: "l"(o1), "f"(acc[mi][ni][2]), "f"(acc[mi][ni][3]) : "memory");
        }
    }
}

// ========================== B-operand prep (bf16 split) ======================
__global__ void k_prep_cplxB(const float* __restrict__ Are, const float* __restrict__ Aim) {
    int i = blockIdx.x * 256 + threadIdx.x;   // < 262144
    int n = i >> 9, k = i & 511;
    float v;
    if (n < 256) v = (k < 256) ? Are[n*256 + k] : -Aim[n*256 + (k-256)];
    else {
        int n2 = n - 256;
        v = (k < 256) ? Aim[n2*256 + k] : Are[n2*256 + (k-256)];
    }
    __nv_bfloat16 h = __float2bfloat16(v);
    d_Bh[BOFF_CPLX + i] = h;
    d_Bl[BOFF_CPLX + i] = __float2bfloat16(v - __bfloat162float(h));
}

__global__ void k_prep_wT(const float* __restrict__ W, int K, int N, int off) {
    int i = blockIdx.x * 256 + threadIdx.x;
    if (i >= N * K) return;
    int n = i / K, k = i % K;
    float v = W[k*N + n];
    __nv_bfloat16 h = __float2bfloat16(v);
    d_Bh[off + i] = h;
    d_Bl[off + i] = __float2bfloat16(v - __bfloat162float(h));
}

// ========================= activation splits (vectorized) ====================
__global__ void k_split_gxy() {
    int idx = blockIdx.x * 256 + threadIdx.x;  // < 2097152
    size_t row = idx >> 5;
    int c = (idx & 31) * 8;
    const float* gx = &d_gX[row * 256 + c];
    const float* gy = &d_gY[row * 256 + c];
    SplitPack px = split8(*(const float4*)gx, *(const float4*)(gx + 4));
    SplitPack py = split8(*(const float4*)gy, *(const float4*)(gy + 4));
    size_t base = row * 768;
    *(uint4*)&d_Ah[base + c]       = px.hi;
    *(uint4*)&d_Al[base + c]       = px.lo;
    *(uint4*)&d_Ah[base + 256 + c] = py.hi;
    *(uint4*)&d_Al[base + 256 + c] = py.lo;
}

__global__ void k_split2(const float* __restrict__ x) {
    int idx = blockIdx.x * 256 + threadIdx.x;  // < 2097152
    size_t row = idx >> 5;
    int c = (idx & 31) * 8;
    size_t o = row * 256 + c;
    float4 xv0 = *(const float4*)&x[o],      xv1 = *(const float4*)&x[o + 4];
    float4 xd0 = *(const float4*)&d_xd[o],   xd1 = *(const float4*)&d_xd[o + 4];
    float4 gx0 = *(const float4*)&d_gX[o],   gx1 = *(const float4*)&d_gX[o + 4];
    float4 gy0 = *(const float4*)&d_gY[o],   gy1 = *(const float4*)&d_gY[o + 4];
    size_t bo = row * 512 + c;
    float4 br0 = *(const float4*)&d_bb[bo],       br1 = *(const float4*)&d_bb[bo + 4];
    float4 bi0 = *(const float4*)&d_bb[bo + 256], bi1 = *(const float4*)&d_bb[bo + 260];
    float4 t0, t1;
    t0.x = tanhf(gx0.x*br0.x + gy0.x*bi0.x);
    t0.y = tanhf(gx0.y*br0.y + gy0.y*bi0.y);
    t0.z = tanhf(gx0.z*br0.z + gy0.z*bi0.z);
    t0.w = tanhf(gx0.w*br0.w + gy0.w*bi0.w);
    t1.x = tanhf(gx1.x*br1.x + gy1.x*bi1.x);
    t1.y = tanhf(gx1.y*br1.y + gy1.y*bi1.y);
    t1.z = tanhf(gx1.z*br1.z + gy1.z*bi1.z);
    t1.w = tanhf(gx1.w*br1.w + gy1.w*bi1.w);
    SplitPack p0 = split8(xv0, xv1);
    SplitPack p1 = split8(xd0, xd1);
    SplitPack p2 = split8(t0, t1);
    size_t base = row * 768;
    *(uint4*)&d_Ah[base + c]       = p0.hi;  *(uint4*)&d_Al[base + c]       = p0.lo;
    *(uint4*)&d_Ah[base + 256 + c] = p1.hi;  *(uint4*)&d_Al[base + 256 + c] = p1.lo;
    *(uint4*)&d_Ah[base + 512 + c] = p2.hi;  *(uint4*)&d_Al[base + 512 + c] = p2.lo;
}

__global__ void k_bnsplit(const float* __restrict__ h, int statoff,
                          const float* __restrict__ g, const float* __restrict__ be) {
    int tid = threadIdx.x;
    __shared__ float sc[256], sh[256];
    {
        float mean = d_stats[statoff + tid] * (1.0f / NN);
        float var  = d_stats[statoff + 256 + tid] * (1.0f / NN) - mean * mean;
        float s = rsqrtf(var + BNEPS) * g[tid];
        sc[tid] = s;
        sh[tid] = be[tid] - mean * s;
    }
    __syncthreads();
    int idx = blockIdx.x * 256 + tid;          // < 2097152
    size_t row = idx >> 5;
    int c = (idx & 31) * 8;
    size_t o = row * 256 + c;
    float4 h0 = *(const float4*)&h[o], h1 = *(const float4*)&h[o + 4];
    float4 v0, v1;
    v0.x = fmaxf(h0.x * sc[c+0] + sh[c+0], 0.f);
    v0.y = fmaxf(h0.y * sc[c+1] + sh[c+1], 0.f);
    v0.z = fmaxf(h0.z * sc[c+2] + sh[c+2], 0.f);
    v0.w = fmaxf(h0.w * sc[c+3] + sh[c+3], 0.f);
    v1.x = fmaxf(h1.x * sc[c+4] + sh[c+4], 0.f);
    v1.y = fmaxf(h1.y * sc[c+5] + sh[c+5], 0.f);
    v1.z = fmaxf(h1.z * sc[c+6] + sh[c+6], 0.f);
    v1.w = fmaxf(h1.w * sc[c+7] + sh[c+7], 0.f);
    SplitPack p = split8(v0, v1);
    size_t base = row * 768;
    *(uint4*)&d_Ah[base + c] = p.hi;
    *(uint4*)&d_Al[base + c] = p.lo;
}

// ========================= generic mma.sync bf16-split GEMM ==================
__global__ __launch_bounds__(256) void k_mma_gemm(
    const __nv_bfloat16* __restrict__ Ah, const __nv_bfloat16* __restrict__ Al, int ldA,
    const __nv_bfloat16* __restrict__ Bh, const __nv_bfloat16* __restrict__ Bl,
    float* __restrict__ out, int ldout, const float* __restrict__ bias, int K,
    float* __restrict__ stats, int bstrideB)
{
    extern __shared__ __align__(16) __nv_bfloat16 sm[];
    int tid = threadIdx.x;
    int wid = tid >> 5, lane = tid & 31;
    int wm = wid & 1, wn = wid >> 1;
    int row0 = blockIdx.x * 128, n0 = blockIdx.y * 128;
    if (bstrideB) {
        int b = row0 / NV;
        Bh += (size_t)b * bstrideB;
        Bl += (size_t)b * bstrideB;
    }

    float acc[4][4][4];
#pragma unroll
    for (int mi = 0; mi < 4; mi++)
#pragma unroll
        for (int ni = 0; ni < 4; ni++)
#pragma unroll
            for (int q = 0; q < 4; q++) acc[mi][ni][q] = 0.f;

    int idx0 = tid * 2, idx1 = tid * 2 + 1;
    int lr0 = idx0 >> 2, ls0 = idx0 & 3;
    int lr1 = idx1 >> 2, ls1 = idx1 & 3;
    uint32_t so0 = (uint32_t)(lr0 * ASTR + ls0 * 8) * 2;
    uint32_t so1 = (uint32_t)(lr1 * ASTR + ls1 * 8) * 2;
    uint32_t smbase = smem_u32(sm);

    const int S = K >> 5;

#define LOADSTAGE(s) do { \
    int buf = (s) & 1; \
    uint32_t sb = smbase + (uint32_t)buf * 4u * TILEEL * 2u; \
    int k0 = (s) << 5; \
    CP_ASYNC(sb + so0, Ah + (size_t)(row0 + lr0) * ldA + k0 + ls0*8); \
    CP_ASYNC(sb + so1, Ah + (size_t)(row0 + lr1) * ldA + k0 + ls1*8); \
    CP_ASYNC(sb + TILEEL*2 + so0, Al + (size_t)(row0 + lr0) * ldA + k0 + ls0*8); \
    CP_ASYNC(sb + TILEEL*2 + so1, Al + (size_t)(row0 + lr1) * ldA + k0 + ls1*8); \
    CP_ASYNC(sb + 2*TILEEL*2 + so0, Bh + (size_t)(n0 + lr0) * K + k0 + ls0*8); \
    CP_ASYNC(sb + 2*TILEEL*2 + so1, Bh + (size_t)(n0 + lr1) * K + k0 + ls1*8); \
    CP_ASYNC(sb + 3*TILEEL*2 + so0, Bl + (size_t)(n0 + lr0) * K + k0 + ls0*8); \
    CP_ASYNC(sb + 3*TILEEL*2 + so1, Bl + (size_t)(n0 + lr1) * K + k0 + ls1*8); \
} while (0)

    LOADSTAGE(0);
    CP_COMMIT();

    int arow = (lane & 15), acol = (lane >> 4) * 8;
    int brow = (lane & 7),  bcol = ((lane >> 3) & 1) * 8;

    for (int s = 0; s < S; s++) {
        if (s + 1 < S) { LOADSTAGE(s + 1); CP_COMMIT(); CP_WAIT(1); }
        else           { CP_WAIT(0); }
        __syncthreads();

        uint32_t sb = smbase + (uint32_t)(s & 1) * 4u * TILEEL * 2u;
        uint32_t Ah_s = sb, Al_s = sb + TILEEL*2, Bh_s = sb + 2*TILEEL*2, Bl_s = sb + 3*TILEEL*2;

#pragma unroll
        for (int ks = 0; ks < 2; ks++) {
            int k0 = ks * 16;
            uint32_t aH[4][4], aL[4][4];
#pragma unroll
            for (int mi = 0; mi < 4; mi++) {
                uint32_t off = (uint32_t)((wm*64 + mi*16 + arow) * ASTR + k0 + acol) * 2;
                ldsm_x4(aH[mi], Ah_s + off);
                ldsm_x4(aL[mi], Al_s + off);
            }
            uint32_t bH[4][2], bL[4][2];
#pragma unroll
            for (int ni = 0; ni < 4; ni++) {
                uint32_t off = (uint32_t)((wn*32 + ni*8 + brow) * ASTR + k0 + bcol) * 2;
                ldsm_x2(bH[ni], Bh_s + off);
                ldsm_x2(bL[ni], Bl_s + off);
            }
#pragma unroll
            for (int mi = 0; mi < 4; mi++)
#pragma unroll
                for (int ni = 0; ni < 4; ni++) {
                    mma16816(acc[mi][ni], aH[mi], bH[ni]);
                    mma16816(acc[mi][ni], aH[mi], bL[ni]);
                    mma16816(acc[mi][ni], aL[mi], bH[ni]);
                }
        }
        __syncthreads();
    }

    // epilogue (+ optional per-column stats)
    int g4 = lane >> 2, t4 = lane & 3;
    float cs[4][2], cq[4][2];
#pragma unroll
    for (int ni = 0; ni < 4; ni++) { cs[ni][0]=cs[ni][1]=cq[ni][0]=cq[ni][1]=0.f; }

#pragma unroll
    for (int mi = 0; mi < 4; mi++) {
        int r = row0 + wm*64 + mi*16 + g4;
#pragma unroll
        for (int ni = 0; ni < 4; ni++) {
            int c = n0 + wn*32 + ni*8 + t4*2;
            float b0 = 0.f, b1 = 0.f;
            if (bias) { b0 = bias[c]; b1 = bias[c+1]; }
            float v0 = acc[mi][ni][0] + b0, v1 = acc[mi][ni][1] + b1;
            float v2 = acc[mi][ni][2] + b0, v3 = acc[mi][ni][3] + b1;
            *(float2*)&out[(size_t)r * ldout + c]     = make_float2(v0, v1);
            *(float2*)&out[(size_t)(r+8) * ldout + c] = make_float2(v2, v3);
            cs[ni][0] += v0 + v2;  cq[ni][0] += v0*v0 + v2*v2;
            cs[ni][1] += v1 + v3;  cq[ni][1] += v1*v1 + v3*v3;
        }
    }
    if (stats) {
#pragma unroll
        for (int ni = 0; ni < 4; ni++) {
#pragma unroll
            for (int h = 0; h < 2; h++) {
                float s = cs[ni][h], q = cq[ni][h];
                s += __shfl_xor_sync(0xFFFFFFFFu, s, 4);
                q += __shfl_xor_sync(0xFFFFFFFFu, q, 4);
                s += __shfl_xor_sync(0xFFFFFFFFu, s, 8);
                q += __shfl_xor_sync(0xFFFFFFFFu, q, 8);
                s += __shfl_xor_sync(0xFFFFFFFFu, s, 16);
                q += __shfl_xor_sync(0xFFFFFFFFu, q, 16);
                if (g4 == 0) {
                    int c = n0 + wn*32 + ni*8 + t4*2 + h;
                    atomicAdd(&stats[c], s);
                    atomicAdd(&stats[256 + c], q);
                }
            }
        }
    }
}

// out = bn(h2) + x
__global__ void k_final(const float* __restrict__ x, const float* __restrict__ g,
                        const float* __restrict__ be, float* __restrict__ out) {
    int tid = threadIdx.x;
    __shared__ float sc[256], sh[256];
    {
        float mean = d_stats[1024 + tid] * (1.0f / NN);
        float var  = d_stats[1280 + tid] * (1.0f / NN) - mean * mean;
        float s = rsqrtf(var + BNEPS) * g[tid];
        sc[tid] = s;
        sh[tid] = be[tid] - mean * s;
    }
    __syncthreads();
    size_t i = (size_t)(blockIdx.x * 256 + tid) * 4;
    int c = (int)(i & 255);
    float4 h  = *(float4*)&d_h2[i];
    float4 xv = *(const float4*)&x[i];
    float4 o;
    o.x = h.x * sc[c+0] + sh[c+0] + xv.x;
    o.y = h.y * sc[c+1] + sh[c+1] + xv.y;
    o.z = h.z * sc[c+2] + sh[c+2] + xv.z;
    o.w = h.w * sc[c+3] + sh[c+3] + xv.w;
    *(float4*)&out[i] = o;
}

// ------------------------------- launch --------------------------------------
extern "C" void kernel_launch(void* const* d_in, const int* in_sizes, int n_in,
                              void* d_out, int out_size) {
    const float* x       = (const float*)d_in[0];
    const float* mass    = (const float*)d_in[1];
    const float* evals   = (const float*)d_in[2];
    const float* evecs   = (const float*)d_in[3];
    const int*   gx_rows = (const int*)  d_in[4];
    const int*   gx_cols = (const int*)  d_in[5];
    const float* gx_vals = (const float*)d_in[6];
    const int*   gy_rows = (const int*)  d_in[7];
    const int*   gy_cols = (const int*)  d_in[8];
    const float* gy_vals = (const float*)d_in[9];
    const float* dt      = (const float*)d_in[10];
    const float* A_re    = (const float*)d_in[11];
    const float* A_im    = (const float*)d_in[12];
    const float* W0      = (const float*)d_in[13];
    const float* b0      = (const float*)d_in[14];
    const float* g0      = (const float*)d_in[15];
    const float* be0     = (const float*)d_in[16];
    const float* W1      = (const float*)d_in[17];
    const float* b1      = (const float*)d_in[18];
    const float* g1      = (const float*)d_in[19];
    const float* be1     = (const float*)d_in[20];
    const float* W2      = (const float*)d_in[21];
    const float* b2      = (const float*)d_in[22];
    const float* g2      = (const float*)d_in[23];
    const float* be2     = (const float*)d_in[24];
    float* out = (float*)d_out;

    static int smem_set = 0;
    if (!smem_set) {
        cudaFuncSetAttribute(k_mma_gemm, cudaFuncAttributeMaxDynamicSharedMemorySize, GEMM_SMEM);
        cudaFuncSetAttribute(k_xspec_mma, cudaFuncAttributeMaxDynamicSharedMemorySize, GEMM_SMEM);
        smem_set = 1;
    }

    __nv_bfloat16 *Ah, *Al, *Bh, *Bl, *eH, *eL, *ytH, *ytL;
    float *bb, *h0, *h1, *h2, *stats, *xd, *gX, *gY;
    cudaGetSymbolAddress((void**)&Ah, d_Ah);
    cudaGetSymbolAddress((void**)&Al, d_Al);
    cudaGetSymbolAddress((void**)&Bh, d_Bh);
    cudaGetSymbolAddress((void**)&Bl, d_Bl);
    cudaGetSymbolAddress((void**)&eH, d_eH);
    cudaGetSymbolAddress((void**)&eL, d_eL);
    cudaGetSymbolAddress((void**)&ytH, d_ytH);
    cudaGetSymbolAddress((void**)&ytL, d_ytL);
    cudaGetSymbolAddress((void**)&bb, d_bb);
    cudaGetSymbolAddress((void**)&h0, d_h0);
    cudaGetSymbolAddress((void**)&h1, d_h1);
    cudaGetSymbolAddress((void**)&h2, d_h2);
    cudaGetSymbolAddress((void**)&stats, d_stats);
    cudaGetSymbolAddress((void**)&xd, d_xd);
    cudaGetSymbolAddress((void**)&gX, d_gX);
    cudaGetSymbolAddress((void**)&gY, d_gY);

    k_zero<<<256, 256>>>();
    // CSR build for both sparse matrices
    k_hist<<<4096, 256>>>(gx_rows, gy_rows);
    k_scan1<<<512, 256>>>();
    k_scan2<<<1, 512>>>();
    k_scan3<<<512, 256>>>();
    k_scatter<<<4096, 256>>>(gx_rows, gy_rows);
    // spectral operand prep (merged evecs read: mt + e)
    k_trans_mevecs<<<dim3(256, 4, 8), 256>>>(evecs, mass);
    k_trans_x<<<dim3(256, 8, 8), 256>>>(x);
    // x_spec (split-K tensor GEMM, atomic accumulate)
    k_xspec_mma<<<dim3(32, 2, 8), 256, GEMM_SMEM>>>();
    k_coefT<<<256, 256>>>(evals, dt);
    // x_diffuse = evecs @ yT^T  (per-batch B)
    k_mma_gemm<<<dim3(512, 2), 256, GEMM_SMEM>>>(eH, eL, NK, ytH, ytL,
                                                 xd, 256, nullptr, NK, nullptr, NC*NK);
    // sparse gradients (CSR gather form)
    k_spmm_csr<<<16384, 256>>>(gx_cols, gx_vals, 0, gX);
    k_spmm_csr<<<16384, 256>>>(gy_cols, gy_vals, 65536, gY);

    // weight prep (small)
    k_prep_cplxB<<<1024, 256>>>(A_re, A_im);
    k_prep_wT<<<768, 256>>>(W0, 768, 256, BOFF_W0);
    k_prep_wT<<<256, 256>>>(W1, 256, 256, BOFF_W1);
    k_prep_wT<<<256, 256>>>(W2, 256, 256, BOFF_W2);

    // complex gradient GEMM: [bre|bim] = [gX|gY] @ B'^T
    k_split_gxy<<<8192, 256>>>();
    k_mma_gemm<<<dim3(512, 4), 256, GEMM_SMEM>>>(Ah, Al, 768, Bh + BOFF_CPLX, Bl + BOFF_CPLX,
                                                 bb, 512, nullptr, 512, nullptr, 0);
    k_split2<<<8192, 256>>>(x);

    // MLP (stats fused into epilogues)
    k_mma_gemm<<<dim3(512, 2), 256, GEMM_SMEM>>>(Ah, Al, 768, Bh + BOFF_W0, Bl + BOFF_W0,
                                                 h0, 256, b0, 768, stats, 0);
    k_bnsplit<<<8192, 256>>>(h0, 0, g0, be0);
    k_mma_gemm<<<dim3(512, 2), 256, GEMM_SMEM>>>(Ah, Al, 768, Bh + BOFF_W1, Bl + BOFF_W1,
                                                 h1, 256, b1, 256, stats + 512, 0);
    k_bnsplit<<<8192, 256>>>(h1, 512, g1, be1);
    k_mma_gemm<<<dim3(512, 2), 256, GEMM_SMEM>>>(Ah, Al, 768, Bh + BOFF_W2, Bl + BOFF_W2,
                                                 h2, 256, b2, 256, stats + 1024, 0);
    k_final<<<16384, 256>>>(x, g2, be2, out);
}